// round 15
// baseline (speedup 1.0000x reference)
#include <cuda_runtime.h>
#include <cuda_bf16.h>
#include <cuda_fp16.h>
#include <math.h>
#include <stdint.h>

#define NN 100000
#define NE 1600000
#define NG 200
#define HID 64
#define NB_SCAN 98  // ceil(NN/1024)

// ---------------- scratch (static device globals; no allocation) ----------------
__device__ int   g_deg[NN];
__device__ int   g_incl[NN];
__device__ int   g_rowptr[NN + 1];
__device__ int   g_cur[NN];
__device__ int   g_bsums[256];
__device__ int   g_csr[NE];
__device__ float g_hA[NN * HID];          // mlp output (fp32, read by pool)
__device__ __half g_h16A[NN * HID];
__device__ __half g_h16B[NN * HID];
__device__ __half g_agg16[NN * 128];

__device__ __forceinline__ float silu_f(float z) { return z / (1.f + __expf(-z)); }

__device__ __forceinline__ uint32_t smem_u32(const void* p) {
    uint32_t a;
    asm("{ .reg .u64 t; cvta.to.shared.u64 t, %1; cvt.u32.u64 %0, t; }" : "=r"(a) : "l"(p));
    return a;
}

// hi = truncate-to-bf16 (bit mask), lo = x - hi rounded to bf16. err <= 2^-15 rel.
__device__ __forceinline__ void split_pack(float4 f, uint32_t& h01, uint32_t& h23,
                                           uint32_t& l01, uint32_t& l23) {
    uint32_t x0 = __float_as_uint(f.x), x1 = __float_as_uint(f.y);
    uint32_t x2 = __float_as_uint(f.z), x3 = __float_as_uint(f.w);
    h01 = __byte_perm(x0, x1, 0x7632);
    h23 = __byte_perm(x2, x3, 0x7632);
    float l0 = f.x - __uint_as_float(x0 & 0xFFFF0000u);
    float l1 = f.y - __uint_as_float(x1 & 0xFFFF0000u);
    float l2 = f.z - __uint_as_float(x2 & 0xFFFF0000u);
    float l3 = f.w - __uint_as_float(x3 & 0xFFFF0000u);
    asm("cvt.rn.bf16x2.f32 %0, %1, %2;" : "=r"(l01) : "f"(l1), "f"(l0));
    asm("cvt.rn.bf16x2.f32 %0, %1, %2;" : "=r"(l23) : "f"(l3), "f"(l2));
}

__device__ __forceinline__ void split_pack2(float a, float b, uint32_t& h01, uint32_t& l01) {
    uint32_t x0 = __float_as_uint(a), x1 = __float_as_uint(b);
    h01 = __byte_perm(x0, x1, 0x7632);
    float l0 = a - __uint_as_float(x0 & 0xFFFF0000u);
    float l1 = b - __uint_as_float(x1 & 0xFFFF0000u);
    asm("cvt.rn.bf16x2.f32 %0, %1, %2;" : "=r"(l01) : "f"(l1), "f"(l0));
}

__device__ __forceinline__ void ldsm4(uint32_t* r, uint32_t addr) {
    asm volatile("ldmatrix.sync.aligned.m8n8.x4.shared.b16 {%0,%1,%2,%3}, [%4];"
                 : "=r"(r[0]), "=r"(r[1]), "=r"(r[2]), "=r"(r[3]) : "r"(addr));
}

__device__ __forceinline__ void mma16816(float* c, const uint32_t* a, uint32_t b0, uint32_t b1) {
    asm volatile(
        "mma.sync.aligned.m16n8k16.row.col.f32.bf16.bf16.f32 "
        "{%0,%1,%2,%3}, {%4,%5,%6,%7}, {%8,%9}, {%0,%1,%2,%3};"
        : "+f"(c[0]), "+f"(c[1]), "+f"(c[2]), "+f"(c[3])
        : "r"(a[0]), "r"(a[1]), "r"(a[2]), "r"(a[3]), "r"(b0), "r"(b1));
}

// ---------------- CSR build ----------------
__global__ void zero_deg_kernel(int* deg) {
    int i = blockIdx.x * blockDim.x + threadIdx.x;
    if (i < NN) deg[i] = 0;
}

__global__ void hist_kernel(const int* __restrict__ ei, int* __restrict__ deg) {
    int e = (blockIdx.x * blockDim.x + threadIdx.x) * 4;
    if (e < NE) {  // NE % 4 == 0
        int4 d4 = *(const int4*)(ei + NE + e);
        atomicAdd(&deg[d4.x], 1);
        atomicAdd(&deg[d4.y], 1);
        atomicAdd(&deg[d4.z], 1);
        atomicAdd(&deg[d4.w], 1);
    }
}

__global__ void scan1_kernel(const int* __restrict__ deg, int* __restrict__ incl,
                             int* __restrict__ bsums) {
    __shared__ int s[1024];
    int tid = threadIdx.x;
    int i = blockIdx.x * 1024 + tid;
    s[tid] = (i < NN) ? deg[i] : 0;
    __syncthreads();
    for (int off = 1; off < 1024; off <<= 1) {
        int v = (tid >= off) ? s[tid - off] : 0;
        __syncthreads();
        s[tid] += v;
        __syncthreads();
    }
    if (i < NN) incl[i] = s[tid];
    if (tid == 1023) bsums[blockIdx.x] = s[1023];
}

// scan3 with fused block-sum prefix scan (each block redundantly scans the 98 sums)
__global__ void scan3_kernel(const int* __restrict__ incl, const int* __restrict__ deg,
                             const int* __restrict__ bsums, int* __restrict__ rowptr,
                             int* __restrict__ cur) {
    __shared__ int sPre[NB_SCAN];
    int tid = threadIdx.x;
    if (tid < NB_SCAN) sPre[tid] = bsums[tid];
    __syncthreads();
    if (tid == 0) {
        int run = 0;
        #pragma unroll 2
        for (int b = 0; b < NB_SCAN; b++) { int t = sPre[b]; sPre[b] = run; run += t; }
    }
    __syncthreads();
    int i = blockIdx.x * blockDim.x + tid;
    if (i < NN) {
        int val = incl[i] + sPre[i >> 10];
        rowptr[i + 1] = val;
        cur[i] = val - deg[i];
    }
    if (i == 0) rowptr[0] = 0;
}

__global__ void scatter_kernel(const int* __restrict__ ei, int* __restrict__ cur,
                               int* __restrict__ csr) {
    int e = (blockIdx.x * blockDim.x + threadIdx.x) * 4;
    if (e < NE) {
        int4 s4 = *(const int4*)(ei + e);
        int4 d4 = *(const int4*)(ei + NE + e);
        csr[atomicAdd(&cur[d4.x], 1)] = s4.x;
        csr[atomicAdd(&cur[d4.y], 1)] = s4.y;
        csr[atomicAdd(&cur[d4.z], 1)] = s4.z;
        csr[atomicAdd(&cur[d4.w], 1)] = s4.w;
    }
}

// ---------------- layer 0 (IN=4): fully fused sage + LN + x_res + silu ----------------
__global__ __launch_bounds__(256) void layer0_kernel(
    const float* __restrict__ x, const int* __restrict__ rowptr, const int* __restrict__ csr,
    const float* __restrict__ Wl0, const float* __restrict__ bl0, const float* __restrict__ Wr0,
    const float* __restrict__ Wres, const float* __restrict__ bres,
    const float* __restrict__ lng, const float* __restrict__ lnb,
    __half* __restrict__ h16out) {
    int tid = threadIdx.x;
    int grp = tid >> 6;
    int l = tid & 63;
    int v = blockIdx.x * 4 + grp;
    bool valid = (v < NN);
    __shared__ float sMx[4][64], sSm[4][64], sAgg[4][8], sX[4][4], sP[4][2][2];
    int start = 0, end = 0;
    if (valid) { start = rowptr[v]; end = rowptr[v + 1]; }
    if (valid && l < 4) sX[grp][l] = x[v * 4 + l];
    int es = l >> 2, dim = l & 3;
    float mx = -INFINITY, sm = 0.f;
    for (int e = start + es; e < end; e += 16) {
        int s = csr[e];
        float val = x[s * 4 + dim];
        mx = fmaxf(mx, val);
        sm += val;
    }
    sMx[grp][l] = mx; sSm[grp][l] = sm;
    __syncthreads();
    if (l < 8) {
        int dd = l & 3;
        int deg = end - start;
        if (l < 4) {
            float m = -INFINITY;
            #pragma unroll
            for (int j = 0; j < 16; j++) m = fmaxf(m, sMx[grp][j * 4 + dd]);
            sAgg[grp][dd] = (deg > 0) ? m : 0.f;
        } else {
            float s2 = 0.f;
            #pragma unroll
            for (int j = 0; j < 16; j++) s2 += sSm[grp][j * 4 + dd];
            sAgg[grp][4 + dd] = s2 / (float)(deg > 0 ? deg : 1);
        }
    }
    __syncthreads();
    float acc = __ldg(bl0 + l);
    #pragma unroll
    for (int k = 0; k < 8; k++) acc += sAgg[grp][k] * __ldg(Wl0 + k * 64 + l);
    float xres = __ldg(bres + l);
    #pragma unroll
    for (int k = 0; k < 4; k++) {
        float xv = sX[grp][k];
        acc += xv * __ldg(Wr0 + k * 64 + l);
        xres += xv * __ldg(Wres + k * 64 + l);
    }
    float s1 = acc, q1 = acc * acc;
    #pragma unroll
    for (int m2 = 1; m2 < 32; m2 <<= 1) {
        s1 += __shfl_xor_sync(0xffffffffu, s1, m2);
        q1 += __shfl_xor_sync(0xffffffffu, q1, m2);
    }
    int w = (tid >> 5) & 1;
    if ((tid & 31) == 0) { sP[grp][w][0] = s1; sP[grp][w][1] = q1; }
    __syncthreads();
    float S = sP[grp][0][0] + sP[grp][1][0];
    float Q = sP[grp][0][1] + sP[grp][1][1];
    float mean = S * (1.f / 64.f);
    float var = Q * (1.f / 64.f) - mean * mean;
    float rstd = rsqrtf(var + 1e-5f);
    float z = (acc - mean) * rstd * __ldg(lng + l) + __ldg(lnb + l) + xres;
    if (valid) h16out[v * 64 + l] = __float2half(silu_f(z));
}

// ---------------- aggregation: uint2 gather (8 B/lane, 2 rows/instr), shfl indices ----
// One warp per node. Lane l holds dims 4*(l&15)..4*(l&15)+3. Half-warp h gathers
// edge 2j+h in step j. Indices: one 32B broadcast load of 8 csr entries + shfl.
__global__ __launch_bounds__(256) void agg_kernel(const __half* __restrict__ h16,
                                                  const int* __restrict__ rowptr,
                                                  const int* __restrict__ csr,
                                                  __half* __restrict__ agg16) {
    int tid = threadIdx.x;
    int warp = tid >> 5;
    int lane = tid & 31;
    int h = lane >> 4;     // half-warp
    int sl = lane & 15;    // uint2 slot: dims 4sl..4sl+3
    int v = blockIdx.x * 8 + warp;
    if (v >= NN) return;
    const uint2* hp2 = (const uint2*)h16;  // node row = 16 uint2
    int start = rowptr[v], end = rowptr[v + 1];
    int deg = end - start;
    float mx0 = -INFINITY, mx1 = -INFINITY, mx2 = -INFINITY, mx3 = -INFINITY;
    float sm0 = 0.f, sm1 = 0.f, sm2 = 0.f, sm3 = 0.f;
    int e = start;
    for (; e + 8 <= end; e += 8) {
        int myi = csr[e + (lane & 7)];  // 8 distinct, 32B, broadcast across warp
        #pragma unroll
        for (int j = 0; j < 4; j++) {
            int idx = __shfl_sync(0xffffffffu, myi, j * 2 + h, 32);
            uint2 d = hp2[idx * 16 + sl];
            float2 f0 = __half22float2(*(__half2*)&d.x);
            float2 f1 = __half22float2(*(__half2*)&d.y);
            mx0 = fmaxf(mx0, f0.x); mx1 = fmaxf(mx1, f0.y);
            mx2 = fmaxf(mx2, f1.x); mx3 = fmaxf(mx3, f1.y);
            sm0 += f0.x; sm1 += f0.y; sm2 += f1.x; sm3 += f1.y;
        }
    }
    // tail: half-warp h handles edge e+h, stepping by 2
    for (; e < end; e += 2) {
        int ee = e + h;
        if (ee < end) {
            int idx = csr[ee];
            uint2 d = hp2[idx * 16 + sl];
            float2 f0 = __half22float2(*(__half2*)&d.x);
            float2 f1 = __half22float2(*(__half2*)&d.y);
            mx0 = fmaxf(mx0, f0.x); mx1 = fmaxf(mx1, f0.y);
            mx2 = fmaxf(mx2, f1.x); mx3 = fmaxf(mx3, f1.y);
            sm0 += f0.x; sm1 += f0.y; sm2 += f1.x; sm3 += f1.y;
        }
    }
    // merge half-warps (same dim mapping, disjoint edges)
    mx0 = fmaxf(mx0, __shfl_xor_sync(0xffffffffu, mx0, 16));
    mx1 = fmaxf(mx1, __shfl_xor_sync(0xffffffffu, mx1, 16));
    mx2 = fmaxf(mx2, __shfl_xor_sync(0xffffffffu, mx2, 16));
    mx3 = fmaxf(mx3, __shfl_xor_sync(0xffffffffu, mx3, 16));
    sm0 += __shfl_xor_sync(0xffffffffu, sm0, 16);
    sm1 += __shfl_xor_sync(0xffffffffu, sm1, 16);
    sm2 += __shfl_xor_sync(0xffffffffu, sm2, 16);
    sm3 += __shfl_xor_sync(0xffffffffu, sm3, 16);
    float inv = 1.f / (float)(deg > 0 ? deg : 1);
    uint2* arow2 = (uint2*)(agg16 + (long)v * 128);  // 32 uint2: [mx 0..15 | mean 16..31]
    if (h == 0) {
        float a0 = (deg > 0) ? mx0 : 0.f, a1 = (deg > 0) ? mx1 : 0.f;
        float a2 = (deg > 0) ? mx2 : 0.f, a3 = (deg > 0) ? mx3 : 0.f;
        __half2 p0 = __floats2half2_rn(a0, a1), p1 = __floats2half2_rn(a2, a3);
        uint2 o;
        o.x = *(uint32_t*)&p0; o.y = *(uint32_t*)&p1;
        arow2[sl] = o;
    } else {
        __half2 p0 = __floats2half2_rn(sm0 * inv, sm1 * inv);
        __half2 p1 = __floats2half2_rn(sm2 * inv, sm3 * inv);
        uint2 o;
        o.x = *(uint32_t*)&p0; o.y = *(uint32_t*)&p1;
        arow2[16 + sl] = o;
    }
}

// ---------------- sage hidden layer: mma.sync bf16 hi/lo, M=64, 2/SM, reg-prefetch ---
#define MMA_SMEM 104448
#define NTILE64 ((NN + 63) / 64)
__global__ __launch_bounds__(256) void sage_mma_kernel(
    const __half* __restrict__ agg16, const __half* __restrict__ h16in,
    const float* __restrict__ Wl, const float* __restrict__ bl, const float* __restrict__ Wr,
    const float* __restrict__ lng, const float* __restrict__ lnb,
    __half* __restrict__ h16out) {
    extern __shared__ char smem[];
    uint32_t sbase = smem_u32(smem);
    const uint32_t SAH = sbase, SAL = sbase + 25600;
    const uint32_t SBH = sbase + 51200, SBL = sbase + 76800;
    float2* sRed = (float2*)(smem + 102400);  // [64 rows][4 col-groups]
    int tid = threadIdx.x;

    // ---- stage weights ONCE per block: B[n=64][k=192] hi/lo, row stride 400 B
    {
        int n = tid >> 2, q = tid & 3;
        uint32_t dh = SBH + n * 400 + q * 96;
        uint32_t dl = SBL + n * 400 + q * 96;
        #pragma unroll
        for (int it = 0; it < 12; it++) {
            int k = q * 48 + it * 4;
            float4 f;
            f.x = (k + 0 < 128) ? __ldg(Wl + (k + 0) * 64 + n) : __ldg(Wr + (k - 128) * 64 + n);
            f.y = (k + 1 < 128) ? __ldg(Wl + (k + 1) * 64 + n) : __ldg(Wr + (k - 127) * 64 + n);
            f.z = (k + 2 < 128) ? __ldg(Wl + (k + 2) * 64 + n) : __ldg(Wr + (k - 126) * 64 + n);
            f.w = (k + 3 < 128) ? __ldg(Wl + (k + 3) * 64 + n) : __ldg(Wr + (k - 125) * 64 + n);
            uint32_t h01, h23, l01, l23;
            split_pack(f, h01, h23, l01, l23);
            asm volatile("st.shared.v2.u32 [%0], {%1,%2};" :: "r"(dh + it * 8), "r"(h01), "r"(h23));
            asm volatile("st.shared.v2.u32 [%0], {%1,%2};" :: "r"(dl + it * 8), "r"(l01), "r"(l23));
        }
    }

    int w = tid >> 5, lane = tid & 31;
    int mblk = (w & 1) * 32, nblk = (w >> 1) * 16;
    int wg = w >> 1;  // column group 0..3
    uint32_t aRel = (uint32_t)((mblk + (lane & 15)) * 400 + ((lane >> 4) & 1) * 16);
    uint32_t bRel = (uint32_t)((nblk + ((lane >> 4) & 1) * 8 + (lane & 7)) * 400 +
                               ((lane >> 3) & 1) * 16);
    int c0 = nblk + (lane & 3) * 2;
    float2 blv[2], gv[2], bbv[2];
    #pragma unroll
    for (int nt = 0; nt < 2; nt++) {
        blv[nt] = *(const float2*)(bl + c0 + nt * 8);
        gv[nt] = *(const float2*)(lng + c0 + nt * 8);
        bbv[nt] = *(const float2*)(lnb + c0 + nt * 8);
    }
    int sgrow = tid >> 2, sq = tid & 3;
    uint32_t dhA = SAH + sgrow * 400 + sq * 96;
    uint32_t dlA = SAL + sgrow * 400 + sq * 96;

    // ---- register prefetch of A panel rows (12 x 8B per thread)
    uint2 pre[12];
    {
        int grow = blockIdx.x * 64 + sgrow;
        bool valid = grow < NN;
        const uint2* ar = (const uint2*)(agg16 + (long)grow * 128);
        const uint2* hr = (const uint2*)(h16in + (long)grow * 64);
        #pragma unroll
        for (int it = 0; it < 12; it++) {
            int c = sq * 48 + it * 4;
            uint2 vv = make_uint2(0u, 0u);
            if (valid) vv = (c < 128) ? ar[c >> 2] : hr[(c - 128) >> 2];
            pre[it] = vv;
        }
    }

    for (int t = blockIdx.x; t < NTILE64; t += gridDim.x) {
        __syncthreads();
        int base = t * 64;
        // ---- STS from prefetched registers (convert fp16 -> bf16 hi/lo)
        #pragma unroll
        for (int it = 0; it < 12; it++) {
            __half2 a0 = *(__half2*)&pre[it].x;
            __half2 a1 = *(__half2*)&pre[it].y;
            float2 p0 = __half22float2(a0), p1 = __half22float2(a1);
            float4 f = make_float4(p0.x, p0.y, p1.x, p1.y);
            uint32_t h01, h23, l01, l23;
            split_pack(f, h01, h23, l01, l23);
            asm volatile("st.shared.v2.u32 [%0], {%1,%2};" :: "r"(dhA + it * 8), "r"(h01), "r"(h23));
            asm volatile("st.shared.v2.u32 [%0], {%1,%2};" :: "r"(dlA + it * 8), "r"(l01), "r"(l23));
        }
        __syncthreads();
        // ---- issue loads for next tile (latency hidden under MMA below)
        int tn = t + gridDim.x;
        if (tn < NTILE64) {
            int grow = tn * 64 + sgrow;
            bool valid = grow < NN;
            const uint2* ar = (const uint2*)(agg16 + (long)grow * 128);
            const uint2* hr = (const uint2*)(h16in + (long)grow * 64);
            #pragma unroll
            for (int it = 0; it < 12; it++) {
                int c = sq * 48 + it * 4;
                uint2 vv = make_uint2(0u, 0u);
                if (valid) vv = (c < 128) ? ar[c >> 2] : hr[(c - 128) >> 2];
                pre[it] = vv;
            }
        }

        float acc[2][2][4];
        #pragma unroll
        for (int a = 0; a < 2; a++)
            #pragma unroll
            for (int b = 0; b < 2; b++)
                #pragma unroll
                for (int c = 0; c < 4; c++) acc[a][b][c] = 0.f;

        #pragma unroll
        for (int s = 0; s < 12; s++) {
            uint32_t ko = (uint32_t)(s * 32);
            uint32_t ah0[4], ah1[4], al0[4], al1[4];
            ldsm4(ah0, SAH + aRel + ko);
            ldsm4(ah1, SAH + aRel + 6400 + ko);
            ldsm4(al0, SAL + aRel + ko);
            ldsm4(al1, SAL + aRel + 6400 + ko);
            uint32_t bh[4], bL[4];
            ldsm4(bh, SBH + bRel + ko);
            ldsm4(bL, SBL + bRel + ko);
            #pragma unroll
            for (int nt = 0; nt < 2; nt++) {
                uint32_t bhx0 = bh[nt * 2], bhx1 = bh[nt * 2 + 1];
                uint32_t blx0 = bL[nt * 2], blx1 = bL[nt * 2 + 1];
                mma16816(acc[0][nt], ah0, bhx0, bhx1);
                mma16816(acc[0][nt], ah0, blx0, blx1);
                mma16816(acc[0][nt], al0, bhx0, bhx1);
                mma16816(acc[1][nt], ah1, bhx0, bhx1);
                mma16816(acc[1][nt], ah1, blx0, blx1);
                mma16816(acc[1][nt], al1, bhx0, bhx1);
            }
        }

        #pragma unroll
        for (int mt = 0; mt < 2; mt++)
            #pragma unroll
            for (int nt = 0; nt < 2; nt++) {
                acc[mt][nt][0] += blv[nt].x; acc[mt][nt][1] += blv[nt].y;
                acc[mt][nt][2] += blv[nt].x; acc[mt][nt][3] += blv[nt].y;
            }
        #pragma unroll
        for (int mt = 0; mt < 2; mt++) {
            #pragma unroll
            for (int h = 0; h < 2; h++) {
                float s = 0.f, q = 0.f;
                #pragma unroll
                for (int nt = 0; nt < 2; nt++) {
                    float v0 = acc[mt][nt][h * 2], v1 = acc[mt][nt][h * 2 + 1];
                    s += v0 + v1;
                    q += v0 * v0 + v1 * v1;
                }
                s += __shfl_xor_sync(0xffffffffu, s, 1);
                q += __shfl_xor_sync(0xffffffffu, q, 1);
                s += __shfl_xor_sync(0xffffffffu, s, 2);
                q += __shfl_xor_sync(0xffffffffu, q, 2);
                if ((lane & 3) == 0) {
                    int r = mblk + mt * 16 + h * 8 + (lane >> 2);
                    sRed[r * 4 + wg] = make_float2(s, q);
                }
            }
        }
        __syncthreads();
        #pragma unroll
        for (int mt = 0; mt < 2; mt++) {
            #pragma unroll
            for (int h = 0; h < 2; h++) {
                int r = mblk + mt * 16 + h * 8 + (lane >> 2);
                float2 p0 = sRed[r * 4 + 0], p1 = sRed[r * 4 + 1];
                float2 p2 = sRed[r * 4 + 2], p3 = sRed[r * 4 + 3];
                float S = (p0.x + p1.x) + (p2.x + p3.x);
                float Q = (p0.y + p1.y) + (p2.y + p3.y);
                float mean = S * (1.f / 64.f);
                float var = Q * (1.f / 64.f) - mean * mean;
                float rstd = rsqrtf(var + 1e-5f);
                int grow = base + r;
                if (grow < NN) {
                    __half2* orow16 = (__half2*)(h16out + (long)grow * 64);
                    const __half2* rrow = (const __half2*)(h16in + (long)grow * 64);
                    #pragma unroll
                    for (int nt = 0; nt < 2; nt++) {
                        float2 res = __half22float2(rrow[(c0 + nt * 8) >> 1]);
                        float v0 = acc[mt][nt][h * 2], v1 = acc[mt][nt][h * 2 + 1];
                        float ox = silu_f((v0 - mean) * rstd * gv[nt].x + bbv[nt].x + res.x);
                        float oy = silu_f((v1 - mean) * rstd * gv[nt].y + bbv[nt].y + res.y);
                        orow16[(c0 + nt * 8) >> 1] = __floats2half2_rn(ox, oy);
                    }
                }
            }
        }
    }
}

// ---------------- node MLP: mma.sync bf16 hi/lo, 512 thr, dual pipelines, prefetch ---
#define W1H_OFF 0
#define W1L_OFF 36864
#define W2H_OFF 73728
#define W2L_OFF 107520
#define AH_OFF  141312
#define AL_OFF  150528
#define TH_OFF  159744
#define TL_OFF  193536
#define RED_OFF 227328
#define MLP2_SMEM 231424
#define NTILE_MLP ((NN + 63) / 64)  // 1563
__global__ __launch_bounds__(512) void mlp_mma_kernel(
    const __half* __restrict__ h16in, const float* __restrict__ W1, const float* __restrict__ b1,
    const float* __restrict__ gg, const float* __restrict__ bn,
    const float* __restrict__ W2, const float* __restrict__ b2, float* __restrict__ hout) {
    extern __shared__ char smem[];
    uint32_t sb = smem_u32(smem);
    float2* sRed = (float2*)(smem + RED_OFF);  // [64 rows][8 warps-in-half]
    int tid = threadIdx.x;
    int w = tid >> 5, lane = tid & 31;
    int halfsel = w >> 3;   // 0: rows 0..31, 1: rows 32..63
    int wl = w & 7;         // warp within half

    // ---- stage weights (threads 0..255 only; once per block)
    if (tid < 256) {
        int n = tid;
        uint32_t dh = sb + W1H_OFF + n * 144;
        uint32_t dl = sb + W1L_OFF + n * 144;
        #pragma unroll
        for (int it = 0; it < 16; it++) {
            int k = it * 4;
            float4 f;
            f.x = __ldg(W1 + (k + 0) * 256 + n);
            f.y = __ldg(W1 + (k + 1) * 256 + n);
            f.z = __ldg(W1 + (k + 2) * 256 + n);
            f.w = __ldg(W1 + (k + 3) * 256 + n);
            uint32_t h01, h23, l01, l23;
            split_pack(f, h01, h23, l01, l23);
            asm volatile("st.shared.v2.u32 [%0], {%1,%2};" :: "r"(dh + k * 2), "r"(h01), "r"(h23));
            asm volatile("st.shared.v2.u32 [%0], {%1,%2};" :: "r"(dl + k * 2), "r"(l01), "r"(l23));
        }
        int n2 = tid & 63, kq = tid >> 6;  // kq 0..3
        uint32_t dh2 = sb + W2H_OFF + n2 * 528 + kq * 128;
        uint32_t dl2 = sb + W2L_OFF + n2 * 528 + kq * 128;
        #pragma unroll
        for (int it = 0; it < 16; it++) {
            int k = kq * 64 + it * 4;
            float4 f;
            f.x = __ldg(W2 + (k + 0) * 64 + n2);
            f.y = __ldg(W2 + (k + 1) * 64 + n2);
            f.z = __ldg(W2 + (k + 2) * 64 + n2);
            f.w = __ldg(W2 + (k + 3) * 64 + n2);
            uint32_t h01, h23, l01, l23;
            split_pack(f, h01, h23, l01, l23);
            asm volatile("st.shared.v2.u32 [%0], {%1,%2};" :: "r"(dh2 + it * 8), "r"(h01), "r"(h23));
            asm volatile("st.shared.v2.u32 [%0], {%1,%2};" :: "r"(dl2 + it * 8), "r"(l01), "r"(l23));
        }
    }

    int c0w = wl * 32 + (lane & 3) * 2;
    float2 b1v[4], gv[4], bnv[4];
    #pragma unroll
    for (int nt = 0; nt < 4; nt++) {
        b1v[nt] = *(const float2*)(b1 + c0w + nt * 8);
        gv[nt] = *(const float2*)(gg + c0w + nt * 8);
        bnv[nt] = *(const float2*)(bn + c0w + nt * 8);
    }
    int rbase = halfsel * 32;  // local row base of this half
    int mblk2 = rbase + (wl & 1) * 16, nblk2 = (wl >> 1) * 16;
    int c02 = nblk2 + (lane & 3) * 2;
    float2 b2v[2];
    b2v[0] = *(const float2*)(b2 + c02);
    b2v[1] = *(const float2*)(b2 + c02 + 8);

    uint32_t aRel = (uint32_t)((rbase + (lane & 15)) * 144 + ((lane >> 4) & 1) * 16);
    uint32_t bRel = (uint32_t)((wl * 32 + ((lane >> 4) & 1) * 8 + (lane & 7)) * 144 +
                               ((lane >> 3) & 1) * 16);
    uint32_t aRel2 = (uint32_t)((mblk2 + (lane & 15)) * 528 + ((lane >> 4) & 1) * 16);
    uint32_t bRel2 = (uint32_t)((nblk2 + ((lane >> 4) & 1) * 8 + (lane & 7)) * 528 +
                                ((lane >> 3) & 1) * 16);
    int srow = tid >> 3, sci = tid & 7;
    uint32_t dA = (uint32_t)(srow * 144 + sci * 16);

    // ---- register prefetch of A rows (16 B per thread)
    uint4 preA;
    {
        int grow = blockIdx.x * 64 + srow;
        preA = make_uint4(0u, 0u, 0u, 0u);
        if (grow < NN)
            preA = *(const uint4*)((const __half2*)(h16in + (long)grow * 64) + sci * 4);
    }

    for (int t = blockIdx.x; t < NTILE_MLP; t += gridDim.x) {
        __syncthreads();
        int base = t * 64;
        // ---- STS from prefetched registers
        {
            __half2 a0 = *(__half2*)&preA.x, a1 = *(__half2*)&preA.y;
            __half2 a2 = *(__half2*)&preA.z, a3 = *(__half2*)&preA.w;
            float2 p0 = __half22float2(a0), p1 = __half22float2(a1);
            float2 p2 = __half22float2(a2), p3 = __half22float2(a3);
            float4 f0 = make_float4(p0.x, p0.y, p1.x, p1.y);
            float4 f1 = make_float4(p2.x, p2.y, p3.x, p3.y);
            uint32_t h01, h23, l01, l23;
            split_pack(f0, h01, h23, l01, l23);
            asm volatile("st.shared.v2.u32 [%0], {%1,%2};" :: "r"(sb + AH_OFF + dA), "r"(h01), "r"(h23));
            asm volatile("st.shared.v2.u32 [%0], {%1,%2};" :: "r"(sb + AL_OFF + dA), "r"(l01), "r"(l23));
            split_pack(f1, h01, h23, l01, l23);
            asm volatile("st.shared.v2.u32 [%0], {%1,%2};" :: "r"(sb + AH_OFF + dA + 8), "r"(h01), "r"(h23));
            asm volatile("st.shared.v2.u32 [%0], {%1,%2};" :: "r"(sb + AL_OFF + dA + 8), "r"(l01), "r"(l23));
        }
        __syncthreads();
        // ---- issue loads for next tile
        int tn = t + gridDim.x;
        if (tn < NTILE_MLP) {
            int grow = tn * 64 + srow;
            preA = make_uint4(0u, 0u, 0u, 0u);
            if (grow < NN)
                preA = *(const uint4*)((const __half2*)(h16in + (long)grow * 64) + sci * 4);
        }

        // ---- G1: this half's 32 rows x 256 cols, warp covers 32r x 32c
        float acc[2][4][4];
        #pragma unroll
        for (int a = 0; a < 2; a++)
            #pragma unroll
            for (int b = 0; b < 4; b++)
                #pragma unroll
                for (int c = 0; c < 4; c++) acc[a][b][c] = 0.f;
        #pragma unroll
        for (int s = 0; s < 4; s++) {
            uint32_t ko = (uint32_t)(s * 32);
            uint32_t ah0[4], ah1[4], al0[4], al1[4];
            ldsm4(ah0, sb + AH_OFF + aRel + ko);
            ldsm4(ah1, sb + AH_OFF + aRel + 2304 + ko);
            ldsm4(al0, sb + AL_OFF + aRel + ko);
            ldsm4(al1, sb + AL_OFF + aRel + 2304 + ko);
            uint32_t bh0[4], bh1[4], bL0[4], bL1[4];
            ldsm4(bh0, sb + W1H_OFF + bRel + ko);
            ldsm4(bh1, sb + W1H_OFF + bRel + 2304 + ko);
            ldsm4(bL0, sb + W1L_OFF + bRel + ko);
            ldsm4(bL1, sb + W1L_OFF + bRel + 2304 + ko);
            #pragma unroll
            for (int nt = 0; nt < 4; nt++) {
                uint32_t bhx0 = (nt < 2) ? bh0[(nt & 1) * 2] : bh1[(nt & 1) * 2];
                uint32_t bhx1 = (nt < 2) ? bh0[(nt & 1) * 2 + 1] : bh1[(nt & 1) * 2 + 1];
                uint32_t blx0 = (nt < 2) ? bL0[(nt & 1) * 2] : bL1[(nt & 1) * 2];
                uint32_t blx1 = (nt < 2) ? bL0[(nt & 1) * 2 + 1] : bL1[(nt & 1) * 2 + 1];
                mma16816(acc[0][nt], ah0, bhx0, bhx1);
                mma16816(acc[0][nt], ah0, blx0, blx1);
                mma16816(acc[0][nt], al0, bhx0, bhx1);
                mma16816(acc[1][nt], ah1, bhx0, bhx1);
                mma16816(acc[1][nt], ah1, blx0, blx1);
                mma16816(acc[1][nt], al1, bhx0, bhx1);
            }
        }
        #pragma unroll
        for (int mt = 0; mt < 2; mt++) {
            #pragma unroll
            for (int nt = 0; nt < 4; nt++) {
                acc[mt][nt][0] = silu_f(acc[mt][nt][0] + b1v[nt].x);
                acc[mt][nt][1] = silu_f(acc[mt][nt][1] + b1v[nt].y);
                acc[mt][nt][2] = silu_f(acc[mt][nt][2] + b1v[nt].x);
                acc[mt][nt][3] = silu_f(acc[mt][nt][3] + b1v[nt].y);
            }
        }
        #pragma unroll
        for (int mt = 0; mt < 2; mt++) {
            #pragma unroll
            for (int h = 0; h < 2; h++) {
                float s = 0.f, q = 0.f;
                #pragma unroll
                for (int nt = 0; nt < 4; nt++) {
                    float v0 = acc[mt][nt][h * 2], v1 = acc[mt][nt][h * 2 + 1];
                    s += v0 + v1;
                    q += v0 * v0 + v1 * v1;
                }
                s += __shfl_xor_sync(0xffffffffu, s, 1);
                q += __shfl_xor_sync(0xffffffffu, q, 1);
                s += __shfl_xor_sync(0xffffffffu, s, 2);
                q += __shfl_xor_sync(0xffffffffu, q, 2);
                if ((lane & 3) == 0) {
                    int r = rbase + mt * 16 + h * 8 + (lane >> 2);
                    sRed[r * 8 + wl] = make_float2(s, q);
                }
            }
        }
        __syncthreads();
        #pragma unroll
        for (int mt = 0; mt < 2; mt++) {
            #pragma unroll
            for (int h = 0; h < 2; h++) {
                int r = rbase + mt * 16 + h * 8 + (lane >> 2);
                float S = 0.f, Q = 0.f;
                #pragma unroll
                for (int ww = 0; ww < 8; ww++) {
                    float2 p = sRed[r * 8 + ww];
                    S += p.x; Q += p.y;
                }
                float mean = S * (1.f / 256.f);
                float var = Q * (1.f / 256.f) - mean * mean;
                float rstd = rsqrtf(var + 1e-5f);
                #pragma unroll
                for (int nt = 0; nt < 4; nt++) {
                    float n0 = (acc[mt][nt][h * 2] - mean) * rstd * gv[nt].x + bnv[nt].x;
                    float n1 = (acc[mt][nt][h * 2 + 1] - mean) * rstd * gv[nt].y + bnv[nt].y;
                    uint32_t h01, l01;
                    split_pack2(n0, n1, h01, l01);
                    uint32_t d = (uint32_t)(r * 528 + (c0w + nt * 8) * 2);
                    asm volatile("st.shared.b32 [%0], %1;" :: "r"(sb + TH_OFF + d), "r"(h01));
                    asm volatile("st.shared.b32 [%0], %1;" :: "r"(sb + TL_OFF + d), "r"(l01));
                }
            }
        }
        __syncthreads();

        // ---- G2: this half's 32 rows x 64 cols, warp covers 16r x 16c
        float acc2[2][4];
        #pragma unroll
        for (int a = 0; a < 2; a++)
            #pragma unroll
            for (int c = 0; c < 4; c++) acc2[a][c] = 0.f;
        #pragma unroll
        for (int s = 0; s < 16; s++) {
            uint32_t ko = (uint32_t)(s * 32);
            uint32_t ah[4], al[4], bh[4], bL[4];
            ldsm4(ah, sb + TH_OFF + aRel2 + ko);
            ldsm4(al, sb + TL_OFF + aRel2 + ko);
            ldsm4(bh, sb + W2H_OFF + bRel2 + ko);
            ldsm4(bL, sb + W2L_OFF + bRel2 + ko);
            #pragma unroll
            for (int nt = 0; nt < 2; nt++) {
                uint32_t bhx0 = bh[nt * 2], bhx1 = bh[nt * 2 + 1];
                uint32_t blx0 = bL[nt * 2], blx1 = bL[nt * 2 + 1];
                mma16816(acc2[nt], ah, bhx0, bhx1);
                mma16816(acc2[nt], ah, blx0, blx1);
                mma16816(acc2[nt], al, bhx0, bhx1);
            }
        }
        #pragma unroll
        for (int nt = 0; nt < 2; nt++) {
            #pragma unroll
            for (int h = 0; h < 2; h++) {
                int r = mblk2 + h * 8 + (lane >> 2);
                int grow = base + r;
                if (grow < NN) {
                    int col = c02 + nt * 8;
                    float2 o;
                    o.x = acc2[nt][h * 2] + b2v[nt].x;
                    o.y = acc2[nt][h * 2 + 1] + b2v[nt].y;
                    *(float2*)(hout + (long)grow * 64 + col) = o;
                }
            }
        }
    }
}

// ---------------- fused pooling + readout: one block per graph ----------------
__global__ __launch_bounds__(256) void pool_readout_kernel(
    const float* __restrict__ h, const float* __restrict__ x, const int* __restrict__ ptr,
    const float* __restrict__ W1, const float* __restrict__ b1,
    const float* __restrict__ gg, const float* __restrict__ bn,
    const float* __restrict__ W2, const float* __restrict__ b2, float* __restrict__ out) {
    int g = blockIdx.x;
    int start = ptr[g], end = ptr[g + 1];
    int tid = threadIdx.x;
    __shared__ float so[196];
    __shared__ float sS[4][64], sM[4][64];
    __shared__ float red[256];
    __shared__ float ws[8][2];
    __shared__ float stats[2];
    {
        int rl = tid >> 6, d = tid & 63;
        float sm = 0.f, mx = -INFINITY;
        for (int r = start + rl; r < end; r += 4) {
            float v = h[(long)r * 64 + d];
            sm += v;
            mx = fmaxf(mx, v);
        }
        sS[rl][d] = sm; sM[rl][d] = mx;
    }
    __syncthreads();
    if (tid < 64) {
        float s = sS[0][tid] + sS[1][tid] + sS[2][tid] + sS[3][tid];
        float m = fmaxf(fmaxf(sM[0][tid], sM[1][tid]), fmaxf(sM[2][tid], sM[3][tid]));
        int cnt = end - start;
        float mean = s / (float)(cnt > 0 ? cnt : 1);
        if (m == -INFINITY) m = 0.f;
        so[tid] = mean;
        so[64 + tid] = m;
        so[128 + tid] = s;
    }
    if (tid < 4) so[192 + tid] = x[(long)start * 4 + tid];
    __syncthreads();
    float acc = __ldg(b1 + tid);
    #pragma unroll 4
    for (int k = 0; k < 196; k++) acc += so[k] * __ldg(W1 + k * 256 + tid);
    float s = silu_f(acc);
    float ls = s, lq = s * s;
    #pragma unroll
    for (int m2 = 1; m2 < 32; m2 <<= 1) {
        ls += __shfl_xor_sync(0xffffffffu, ls, m2);
        lq += __shfl_xor_sync(0xffffffffu, lq, m2);
    }
    int w = tid >> 5;
    if ((tid & 31) == 0) { ws[w][0] = ls; ws[w][1] = lq; }
    __syncthreads();
    if (tid == 0) {
        float S = 0.f, Q = 0.f;
        for (int i = 0; i < 8; i++) { S += ws[i][0]; Q += ws[i][1]; }
        stats[0] = S; stats[1] = Q;
    }
    __syncthreads();
    float mean = stats[0] * (1.f / 256.f);
    float var = stats[1] * (1.f / 256.f) - mean * mean;
    float rstd = rsqrtf(var + 1e-5f);
    float n = (s - mean) * rstd * __ldg(gg + tid) + __ldg(bn + tid);
    float4 w2 = *(const float4*)(W2 + tid * 4);
    float p[4] = {n * w2.x, n * w2.y, n * w2.z, n * w2.w};
    for (int j = 0; j < 4; j++) {
        red[tid] = p[j];
        __syncthreads();
        for (int st = 128; st > 0; st >>= 1) {
            if (tid < st) red[tid] += red[tid + st];
            __syncthreads();
        }
        if (tid == 0) out[g * 4 + j] = red[0] + __ldg(b2 + j);
        __syncthreads();
    }
}

// ---------------- launch ----------------
extern "C" void kernel_launch(void* const* d_in, const int* in_sizes, int n_in,
                              void* d_out, int out_size) {
    const float* x      = (const float*)d_in[0];
    const int*   ei     = (const int*)d_in[1];
    const int*   ptr    = (const int*)d_in[3];
    const float* Wl0    = (const float*)d_in[4];
    const float* bl0    = (const float*)d_in[5];
    const float* Wr0    = (const float*)d_in[6];
    const float* Wl     = (const float*)d_in[7];
    const float* bl     = (const float*)d_in[8];
    const float* Wr     = (const float*)d_in[9];
    const float* Wres   = (const float*)d_in[10];
    const float* bres   = (const float*)d_in[11];
    const float* ln_g   = (const float*)d_in[12];
    const float* ln_b   = (const float*)d_in[13];
    const float* mlp_W1 = (const float*)d_in[14];
    const float* mlp_b1 = (const float*)d_in[15];
    const float* mlp_g  = (const float*)d_in[16];
    const float* mlp_bn = (const float*)d_in[17];
    const float* mlp_W2 = (const float*)d_in[18];
    const float* mlp_b2 = (const float*)d_in[19];
    const float* ro_W1  = (const float*)d_in[20];
    const float* ro_b1  = (const float*)d_in[21];
    const float* ro_g   = (const float*)d_in[22];
    const float* ro_bn  = (const float*)d_in[23];
    const float* ro_W2  = (const float*)d_in[24];
    const float* ro_b2  = (const float*)d_in[25];
    float* out = (float*)d_out;

    void* p;
    cudaGetSymbolAddress(&p, g_deg);    int* deg = (int*)p;
    cudaGetSymbolAddress(&p, g_incl);   int* incl = (int*)p;
    cudaGetSymbolAddress(&p, g_rowptr); int* rowptr = (int*)p;
    cudaGetSymbolAddress(&p, g_cur);    int* cur = (int*)p;
    cudaGetSymbolAddress(&p, g_bsums);  int* bsums = (int*)p;
    cudaGetSymbolAddress(&p, g_csr);    int* csr = (int*)p;
    cudaGetSymbolAddress(&p, g_hA);     float* hA = (float*)p;
    cudaGetSymbolAddress(&p, g_h16A);   __half* h16A = (__half*)p;
    cudaGetSymbolAddress(&p, g_h16B);   __half* h16B = (__half*)p;
    cudaGetSymbolAddress(&p, g_agg16);  __half* agg16 = (__half*)p;

    cudaFuncSetAttribute(sage_mma_kernel, cudaFuncAttributeMaxDynamicSharedMemorySize, MMA_SMEM);
    cudaFuncSetAttribute(mlp_mma_kernel, cudaFuncAttributeMaxDynamicSharedMemorySize, MLP2_SMEM);

    zero_deg_kernel<<<(NN + 255) / 256, 256>>>(deg);
    hist_kernel<<<(NE / 4 + 255) / 256, 256>>>(ei, deg);
    scan1_kernel<<<(NN + 1023) / 1024, 1024>>>(deg, incl, bsums);
    scan3_kernel<<<(NN + 255) / 256, 256>>>(incl, deg, bsums, rowptr, cur);
    scatter_kernel<<<(NE / 4 + 255) / 256, 256>>>(ei, cur, csr);

    layer0_kernel<<<(NN + 3) / 4, 256>>>(x, rowptr, csr, Wl0, bl0, Wr0, Wres, bres,
                                         ln_g, ln_b, h16A);

    const __half* h16in = h16A;
    __half* h16out = h16B;
    for (int i = 0; i < 3; i++) {
        agg_kernel<<<(NN + 7) / 8, 256>>>(h16in, rowptr, csr, agg16);
        sage_mma_kernel<<<296, 256, MMA_SMEM>>>(agg16, h16in, Wl + i * 128 * 64, bl + i * 64,
                                                Wr + i * 64 * 64, ln_g + (i + 1) * 64,
                                                ln_b + (i + 1) * 64, h16out);
        const __half* tmp16 = h16in;
        h16in = h16out;
        h16out = (__half*)tmp16;
    }
    // h16in == final sage output
    mlp_mma_kernel<<<148, 512, MLP2_SMEM>>>(h16in, mlp_W1, mlp_b1, mlp_g, mlp_bn,
                                            mlp_W2, mlp_b2, hA);
    pool_readout_kernel<<<NG, 256>>>(hA, x, ptr, ro_W1, ro_b1, ro_g, ro_bn,
                                     ro_W2, ro_b2, out);
}

// round 16
// speedup vs baseline: 1.5624x; 1.5624x over previous
#include <cuda_runtime.h>
#include <cuda_bf16.h>
#include <cuda_fp16.h>
#include <math.h>
#include <stdint.h>

#define NN 100000
#define NE 1600000
#define NG 200
#define HID 64
#define NB_SCAN 98  // ceil(NN/1024)

// ---------------- scratch (static device globals; no allocation) ----------------
__device__ int   g_deg[NN];
__device__ int   g_incl[NN];
__device__ int   g_rowptr[NN + 1];
__device__ int   g_cur[NN];
__device__ int   g_bsums[256];
__device__ int   g_csr[NE];
__device__ float g_hA[NN * HID];          // mlp output (fp32, read by pool)
__device__ __half g_h16A[NN * HID];
__device__ __half g_h16B[NN * HID];
__device__ __half g_agg16[NN * 128];

__device__ __forceinline__ float silu_f(float z) { return z / (1.f + __expf(-z)); }

__device__ __forceinline__ uint32_t smem_u32(const void* p) {
    uint32_t a;
    asm("{ .reg .u64 t; cvta.to.shared.u64 t, %1; cvt.u32.u64 %0, t; }" : "=r"(a) : "l"(p));
    return a;
}

// hi = truncate-to-bf16 (bit mask), lo = x - hi rounded to bf16. err <= 2^-15 rel.
__device__ __forceinline__ void split_pack(float4 f, uint32_t& h01, uint32_t& h23,
                                           uint32_t& l01, uint32_t& l23) {
    uint32_t x0 = __float_as_uint(f.x), x1 = __float_as_uint(f.y);
    uint32_t x2 = __float_as_uint(f.z), x3 = __float_as_uint(f.w);
    h01 = __byte_perm(x0, x1, 0x7632);
    h23 = __byte_perm(x2, x3, 0x7632);
    float l0 = f.x - __uint_as_float(x0 & 0xFFFF0000u);
    float l1 = f.y - __uint_as_float(x1 & 0xFFFF0000u);
    float l2 = f.z - __uint_as_float(x2 & 0xFFFF0000u);
    float l3 = f.w - __uint_as_float(x3 & 0xFFFF0000u);
    asm("cvt.rn.bf16x2.f32 %0, %1, %2;" : "=r"(l01) : "f"(l1), "f"(l0));
    asm("cvt.rn.bf16x2.f32 %0, %1, %2;" : "=r"(l23) : "f"(l3), "f"(l2));
}

__device__ __forceinline__ void split_pack2(float a, float b, uint32_t& h01, uint32_t& l01) {
    uint32_t x0 = __float_as_uint(a), x1 = __float_as_uint(b);
    h01 = __byte_perm(x0, x1, 0x7632);
    float l0 = a - __uint_as_float(x0 & 0xFFFF0000u);
    float l1 = b - __uint_as_float(x1 & 0xFFFF0000u);
    asm("cvt.rn.bf16x2.f32 %0, %1, %2;" : "=r"(l01) : "f"(l1), "f"(l0));
}

__device__ __forceinline__ void ldsm4(uint32_t* r, uint32_t addr) {
    asm volatile("ldmatrix.sync.aligned.m8n8.x4.shared.b16 {%0,%1,%2,%3}, [%4];"
                 : "=r"(r[0]), "=r"(r[1]), "=r"(r[2]), "=r"(r[3]) : "r"(addr));
}

__device__ __forceinline__ void mma16816(float* c, const uint32_t* a, uint32_t b0, uint32_t b1) {
    asm volatile(
        "mma.sync.aligned.m16n8k16.row.col.f32.bf16.bf16.f32 "
        "{%0,%1,%2,%3}, {%4,%5,%6,%7}, {%8,%9}, {%0,%1,%2,%3};"
        : "+f"(c[0]), "+f"(c[1]), "+f"(c[2]), "+f"(c[3])
        : "r"(a[0]), "r"(a[1]), "r"(a[2]), "r"(a[3]), "r"(b0), "r"(b1));
}

// ---------------- CSR build ----------------
__global__ void zero_deg_kernel(int* deg) {
    int i = blockIdx.x * blockDim.x + threadIdx.x;
    if (i < NN) deg[i] = 0;
}

__global__ void hist_kernel(const int* __restrict__ ei, int* __restrict__ deg) {
    int e = (blockIdx.x * blockDim.x + threadIdx.x) * 4;
    if (e < NE) {  // NE % 4 == 0
        int4 d4 = *(const int4*)(ei + NE + e);
        atomicAdd(&deg[d4.x], 1);
        atomicAdd(&deg[d4.y], 1);
        atomicAdd(&deg[d4.z], 1);
        atomicAdd(&deg[d4.w], 1);
    }
}

__global__ void scan1_kernel(const int* __restrict__ deg, int* __restrict__ incl,
                             int* __restrict__ bsums) {
    __shared__ int s[1024];
    int tid = threadIdx.x;
    int i = blockIdx.x * 1024 + tid;
    s[tid] = (i < NN) ? deg[i] : 0;
    __syncthreads();
    for (int off = 1; off < 1024; off <<= 1) {
        int v = (tid >= off) ? s[tid - off] : 0;
        __syncthreads();
        s[tid] += v;
        __syncthreads();
    }
    if (i < NN) incl[i] = s[tid];
    if (tid == 1023) bsums[blockIdx.x] = s[1023];
}

// scan3 with fused block-sum prefix scan (each block redundantly scans the 98 sums)
__global__ void scan3_kernel(const int* __restrict__ incl, const int* __restrict__ deg,
                             const int* __restrict__ bsums, int* __restrict__ rowptr,
                             int* __restrict__ cur) {
    __shared__ int sPre[NB_SCAN];
    int tid = threadIdx.x;
    if (tid < NB_SCAN) sPre[tid] = bsums[tid];
    __syncthreads();
    if (tid == 0) {
        int run = 0;
        #pragma unroll 2
        for (int b = 0; b < NB_SCAN; b++) { int t = sPre[b]; sPre[b] = run; run += t; }
    }
    __syncthreads();
    int i = blockIdx.x * blockDim.x + tid;
    if (i < NN) {
        int val = incl[i] + sPre[i >> 10];
        rowptr[i + 1] = val;
        cur[i] = val - deg[i];
    }
    if (i == 0) rowptr[0] = 0;
}

__global__ void scatter_kernel(const int* __restrict__ ei, int* __restrict__ cur,
                               int* __restrict__ csr) {
    int e = (blockIdx.x * blockDim.x + threadIdx.x) * 4;
    if (e < NE) {
        int4 s4 = *(const int4*)(ei + e);
        int4 d4 = *(const int4*)(ei + NE + e);
        csr[atomicAdd(&cur[d4.x], 1)] = s4.x;
        csr[atomicAdd(&cur[d4.y], 1)] = s4.y;
        csr[atomicAdd(&cur[d4.z], 1)] = s4.z;
        csr[atomicAdd(&cur[d4.w], 1)] = s4.w;
    }
}

// ---------------- layer 0 (IN=4): fully fused sage + LN + x_res + silu ----------------
__global__ __launch_bounds__(256) void layer0_kernel(
    const float* __restrict__ x, const int* __restrict__ rowptr, const int* __restrict__ csr,
    const float* __restrict__ Wl0, const float* __restrict__ bl0, const float* __restrict__ Wr0,
    const float* __restrict__ Wres, const float* __restrict__ bres,
    const float* __restrict__ lng, const float* __restrict__ lnb,
    __half* __restrict__ h16out) {
    int tid = threadIdx.x;
    int grp = tid >> 6;
    int l = tid & 63;
    int v = blockIdx.x * 4 + grp;
    bool valid = (v < NN);
    __shared__ float sMx[4][64], sSm[4][64], sAgg[4][8], sX[4][4], sP[4][2][2];
    int start = 0, end = 0;
    if (valid) { start = rowptr[v]; end = rowptr[v + 1]; }
    if (valid && l < 4) sX[grp][l] = x[v * 4 + l];
    int es = l >> 2, dim = l & 3;
    float mx = -INFINITY, sm = 0.f;
    for (int e = start + es; e < end; e += 16) {
        int s = csr[e];
        float val = x[s * 4 + dim];
        mx = fmaxf(mx, val);
        sm += val;
    }
    sMx[grp][l] = mx; sSm[grp][l] = sm;
    __syncthreads();
    if (l < 8) {
        int dd = l & 3;
        int deg = end - start;
        if (l < 4) {
            float m = -INFINITY;
            #pragma unroll
            for (int j = 0; j < 16; j++) m = fmaxf(m, sMx[grp][j * 4 + dd]);
            sAgg[grp][dd] = (deg > 0) ? m : 0.f;
        } else {
            float s2 = 0.f;
            #pragma unroll
            for (int j = 0; j < 16; j++) s2 += sSm[grp][j * 4 + dd];
            sAgg[grp][4 + dd] = s2 / (float)(deg > 0 ? deg : 1);
        }
    }
    __syncthreads();
    float acc = __ldg(bl0 + l);
    #pragma unroll
    for (int k = 0; k < 8; k++) acc += sAgg[grp][k] * __ldg(Wl0 + k * 64 + l);
    float xres = __ldg(bres + l);
    #pragma unroll
    for (int k = 0; k < 4; k++) {
        float xv = sX[grp][k];
        acc += xv * __ldg(Wr0 + k * 64 + l);
        xres += xv * __ldg(Wres + k * 64 + l);
    }
    float s1 = acc, q1 = acc * acc;
    #pragma unroll
    for (int m2 = 1; m2 < 32; m2 <<= 1) {
        s1 += __shfl_xor_sync(0xffffffffu, s1, m2);
        q1 += __shfl_xor_sync(0xffffffffu, q1, m2);
    }
    int w = (tid >> 5) & 1;
    if ((tid & 31) == 0) { sP[grp][w][0] = s1; sP[grp][w][1] = q1; }
    __syncthreads();
    float S = sP[grp][0][0] + sP[grp][1][0];
    float Q = sP[grp][0][1] + sP[grp][1][1];
    float mean = S * (1.f / 64.f);
    float var = Q * (1.f / 64.f) - mean * mean;
    float rstd = rsqrtf(var + 1e-5f);
    float z = (acc - mean) * rstd * __ldg(lng + l) + __ldg(lnb + l) + xres;
    if (valid) h16out[v * 64 + l] = __float2half(silu_f(z));
}

// ---------------- aggregation: fp16 gather, 32 lanes/node, 16/8-wide unroll ----------
__global__ __launch_bounds__(256) void agg_kernel(const __half* __restrict__ h16,
                                                  const int* __restrict__ rowptr,
                                                  const int* __restrict__ csr,
                                                  __half* __restrict__ agg16) {
    int tid = threadIdx.x;
    int grp = tid >> 5;   // 8 nodes per block
    int l = tid & 31;     // half2 lane: dims 2l, 2l+1
    int v = blockIdx.x * 8 + grp;
    if (v >= NN) return;
    const __half2* hp = (const __half2*)h16;
    int start = rowptr[v], end = rowptr[v + 1];
    float mx0 = -INFINITY, mx1 = -INFINITY, sm0 = 0.f, sm1 = 0.f;
    int e = start;
    for (; e + 16 <= end; e += 16) {
        int id[16];
        #pragma unroll
        for (int j = 0; j < 16; j++) id[j] = csr[e + j];
        float2 f[16];
        #pragma unroll
        for (int j = 0; j < 16; j++) f[j] = __half22float2(hp[id[j] * 32 + l]);
        #pragma unroll
        for (int j = 0; j < 16; j++) {
            mx0 = fmaxf(mx0, f[j].x);
            mx1 = fmaxf(mx1, f[j].y);
            sm0 += f[j].x;
            sm1 += f[j].y;
        }
    }
    for (; e + 8 <= end; e += 8) {
        int i0 = csr[e], i1 = csr[e + 1], i2 = csr[e + 2], i3 = csr[e + 3];
        int i4 = csr[e + 4], i5 = csr[e + 5], i6 = csr[e + 6], i7 = csr[e + 7];
        float2 f0 = __half22float2(hp[i0 * 32 + l]);
        float2 f1 = __half22float2(hp[i1 * 32 + l]);
        float2 f2 = __half22float2(hp[i2 * 32 + l]);
        float2 f3 = __half22float2(hp[i3 * 32 + l]);
        float2 f4 = __half22float2(hp[i4 * 32 + l]);
        float2 f5 = __half22float2(hp[i5 * 32 + l]);
        float2 f6 = __half22float2(hp[i6 * 32 + l]);
        float2 f7 = __half22float2(hp[i7 * 32 + l]);
        mx0 = fmaxf(mx0, fmaxf(fmaxf(f0.x, f1.x), fmaxf(f2.x, f3.x)));
        mx0 = fmaxf(mx0, fmaxf(fmaxf(f4.x, f5.x), fmaxf(f6.x, f7.x)));
        mx1 = fmaxf(mx1, fmaxf(fmaxf(f0.y, f1.y), fmaxf(f2.y, f3.y)));
        mx1 = fmaxf(mx1, fmaxf(fmaxf(f4.y, f5.y), fmaxf(f6.y, f7.y)));
        sm0 += ((f0.x + f1.x) + (f2.x + f3.x)) + ((f4.x + f5.x) + (f6.x + f7.x));
        sm1 += ((f0.y + f1.y) + (f2.y + f3.y)) + ((f4.y + f5.y) + (f6.y + f7.y));
    }
    for (; e < end; e++) {
        float2 f = __half22float2(hp[csr[e] * 32 + l]);
        mx0 = fmaxf(mx0, f.x);
        mx1 = fmaxf(mx1, f.y);
        sm0 += f.x;
        sm1 += f.y;
    }
    int deg = end - start;
    float inv = 1.f / (float)(deg > 0 ? deg : 1);
    __half2* arow = (__half2*)(agg16 + (long)v * 128);
    arow[l] = __floats2half2_rn((deg > 0) ? mx0 : 0.f, (deg > 0) ? mx1 : 0.f);
    arow[32 + l] = __floats2half2_rn(sm0 * inv, sm1 * inv);
}

// ---------------- sage hidden layer: mma.sync bf16 hi/lo, M=64, 2/SM, reg-prefetch ---
#define MMA_SMEM 104448
#define NTILE64 ((NN + 63) / 64)
__global__ __launch_bounds__(256) void sage_mma_kernel(
    const __half* __restrict__ agg16, const __half* __restrict__ h16in,
    const float* __restrict__ Wl, const float* __restrict__ bl, const float* __restrict__ Wr,
    const float* __restrict__ lng, const float* __restrict__ lnb,
    __half* __restrict__ h16out) {
    extern __shared__ char smem[];
    uint32_t sbase = smem_u32(smem);
    const uint32_t SAH = sbase, SAL = sbase + 25600;
    const uint32_t SBH = sbase + 51200, SBL = sbase + 76800;
    float2* sRed = (float2*)(smem + 102400);  // [64 rows][4 col-groups]
    int tid = threadIdx.x;

    // ---- stage weights ONCE per block: B[n=64][k=192] hi/lo, row stride 400 B
    {
        int n = tid >> 2, q = tid & 3;
        uint32_t dh = SBH + n * 400 + q * 96;
        uint32_t dl = SBL + n * 400 + q * 96;
        #pragma unroll
        for (int it = 0; it < 12; it++) {
            int k = q * 48 + it * 4;
            float4 f;
            f.x = (k + 0 < 128) ? __ldg(Wl + (k + 0) * 64 + n) : __ldg(Wr + (k - 128) * 64 + n);
            f.y = (k + 1 < 128) ? __ldg(Wl + (k + 1) * 64 + n) : __ldg(Wr + (k - 127) * 64 + n);
            f.z = (k + 2 < 128) ? __ldg(Wl + (k + 2) * 64 + n) : __ldg(Wr + (k - 126) * 64 + n);
            f.w = (k + 3 < 128) ? __ldg(Wl + (k + 3) * 64 + n) : __ldg(Wr + (k - 125) * 64 + n);
            uint32_t h01, h23, l01, l23;
            split_pack(f, h01, h23, l01, l23);
            asm volatile("st.shared.v2.u32 [%0], {%1,%2};" :: "r"(dh + it * 8), "r"(h01), "r"(h23));
            asm volatile("st.shared.v2.u32 [%0], {%1,%2};" :: "r"(dl + it * 8), "r"(l01), "r"(l23));
        }
    }

    int w = tid >> 5, lane = tid & 31;
    int mblk = (w & 1) * 32, nblk = (w >> 1) * 16;
    int wg = w >> 1;  // column group 0..3
    uint32_t aRel = (uint32_t)((mblk + (lane & 15)) * 400 + ((lane >> 4) & 1) * 16);
    uint32_t bRel = (uint32_t)((nblk + ((lane >> 4) & 1) * 8 + (lane & 7)) * 400 +
                               ((lane >> 3) & 1) * 16);
    int c0 = nblk + (lane & 3) * 2;
    float2 blv[2], gv[2], bbv[2];
    #pragma unroll
    for (int nt = 0; nt < 2; nt++) {
        blv[nt] = *(const float2*)(bl + c0 + nt * 8);
        gv[nt] = *(const float2*)(lng + c0 + nt * 8);
        bbv[nt] = *(const float2*)(lnb + c0 + nt * 8);
    }
    int sgrow = tid >> 2, sq = tid & 3;
    uint32_t dhA = SAH + sgrow * 400 + sq * 96;
    uint32_t dlA = SAL + sgrow * 400 + sq * 96;

    // ---- register prefetch of A panel rows (12 x 8B per thread)
    uint2 pre[12];
    {
        int grow = blockIdx.x * 64 + sgrow;
        bool valid = grow < NN;
        const uint2* ar = (const uint2*)(agg16 + (long)grow * 128);
        const uint2* hr = (const uint2*)(h16in + (long)grow * 64);
        #pragma unroll
        for (int it = 0; it < 12; it++) {
            int c = sq * 48 + it * 4;
            uint2 vv = make_uint2(0u, 0u);
            if (valid) vv = (c < 128) ? ar[c >> 2] : hr[(c - 128) >> 2];
            pre[it] = vv;
        }
    }

    for (int t = blockIdx.x; t < NTILE64; t += gridDim.x) {
        __syncthreads();
        int base = t * 64;
        // ---- STS from prefetched registers (convert fp16 -> bf16 hi/lo)
        #pragma unroll
        for (int it = 0; it < 12; it++) {
            __half2 a0 = *(__half2*)&pre[it].x;
            __half2 a1 = *(__half2*)&pre[it].y;
            float2 p0 = __half22float2(a0), p1 = __half22float2(a1);
            float4 f = make_float4(p0.x, p0.y, p1.x, p1.y);
            uint32_t h01, h23, l01, l23;
            split_pack(f, h01, h23, l01, l23);
            asm volatile("st.shared.v2.u32 [%0], {%1,%2};" :: "r"(dhA + it * 8), "r"(h01), "r"(h23));
            asm volatile("st.shared.v2.u32 [%0], {%1,%2};" :: "r"(dlA + it * 8), "r"(l01), "r"(l23));
        }
        __syncthreads();
        // ---- issue loads for next tile (latency hidden under MMA below)
        int tn = t + gridDim.x;
        if (tn < NTILE64) {
            int grow = tn * 64 + sgrow;
            bool valid = grow < NN;
            const uint2* ar = (const uint2*)(agg16 + (long)grow * 128);
            const uint2* hr = (const uint2*)(h16in + (long)grow * 64);
            #pragma unroll
            for (int it = 0; it < 12; it++) {
                int c = sq * 48 + it * 4;
                uint2 vv = make_uint2(0u, 0u);
                if (valid) vv = (c < 128) ? ar[c >> 2] : hr[(c - 128) >> 2];
                pre[it] = vv;
            }
        }

        float acc[2][2][4];
        #pragma unroll
        for (int a = 0; a < 2; a++)
            #pragma unroll
            for (int b = 0; b < 2; b++)
                #pragma unroll
                for (int c = 0; c < 4; c++) acc[a][b][c] = 0.f;

        #pragma unroll
        for (int s = 0; s < 12; s++) {
            uint32_t ko = (uint32_t)(s * 32);
            uint32_t ah0[4], ah1[4], al0[4], al1[4];
            ldsm4(ah0, SAH + aRel + ko);
            ldsm4(ah1, SAH + aRel + 6400 + ko);
            ldsm4(al0, SAL + aRel + ko);
            ldsm4(al1, SAL + aRel + 6400 + ko);
            uint32_t bh[4], bL[4];
            ldsm4(bh, SBH + bRel + ko);
            ldsm4(bL, SBL + bRel + ko);
            #pragma unroll
            for (int nt = 0; nt < 2; nt++) {
                uint32_t bhx0 = bh[nt * 2], bhx1 = bh[nt * 2 + 1];
                uint32_t blx0 = bL[nt * 2], blx1 = bL[nt * 2 + 1];
                mma16816(acc[0][nt], ah0, bhx0, bhx1);
                mma16816(acc[0][nt], ah0, blx0, blx1);
                mma16816(acc[0][nt], al0, bhx0, bhx1);
                mma16816(acc[1][nt], ah1, bhx0, bhx1);
                mma16816(acc[1][nt], ah1, blx0, blx1);
                mma16816(acc[1][nt], al1, bhx0, bhx1);
            }
        }

        #pragma unroll
        for (int mt = 0; mt < 2; mt++)
            #pragma unroll
            for (int nt = 0; nt < 2; nt++) {
                acc[mt][nt][0] += blv[nt].x; acc[mt][nt][1] += blv[nt].y;
                acc[mt][nt][2] += blv[nt].x; acc[mt][nt][3] += blv[nt].y;
            }
        #pragma unroll
        for (int mt = 0; mt < 2; mt++) {
            #pragma unroll
            for (int h = 0; h < 2; h++) {
                float s = 0.f, q = 0.f;
                #pragma unroll
                for (int nt = 0; nt < 2; nt++) {
                    float v0 = acc[mt][nt][h * 2], v1 = acc[mt][nt][h * 2 + 1];
                    s += v0 + v1;
                    q += v0 * v0 + v1 * v1;
                }
                s += __shfl_xor_sync(0xffffffffu, s, 1);
                q += __shfl_xor_sync(0xffffffffu, q, 1);
                s += __shfl_xor_sync(0xffffffffu, s, 2);
                q += __shfl_xor_sync(0xffffffffu, q, 2);
                if ((lane & 3) == 0) {
                    int r = mblk + mt * 16 + h * 8 + (lane >> 2);
                    sRed[r * 4 + wg] = make_float2(s, q);
                }
            }
        }
        __syncthreads();
        #pragma unroll
        for (int mt = 0; mt < 2; mt++) {
            #pragma unroll
            for (int h = 0; h < 2; h++) {
                int r = mblk + mt * 16 + h * 8 + (lane >> 2);
                float2 p0 = sRed[r * 4 + 0], p1 = sRed[r * 4 + 1];
                float2 p2 = sRed[r * 4 + 2], p3 = sRed[r * 4 + 3];
                float S = (p0.x + p1.x) + (p2.x + p3.x);
                float Q = (p0.y + p1.y) + (p2.y + p3.y);
                float mean = S * (1.f / 64.f);
                float var = Q * (1.f / 64.f) - mean * mean;
                float rstd = rsqrtf(var + 1e-5f);
                int grow = base + r;
                if (grow < NN) {
                    __half2* orow16 = (__half2*)(h16out + (long)grow * 64);
                    const __half2* rrow = (const __half2*)(h16in + (long)grow * 64);
                    #pragma unroll
                    for (int nt = 0; nt < 2; nt++) {
                        float2 res = __half22float2(rrow[(c0 + nt * 8) >> 1]);
                        float v0 = acc[mt][nt][h * 2], v1 = acc[mt][nt][h * 2 + 1];
                        float ox = silu_f((v0 - mean) * rstd * gv[nt].x + bbv[nt].x + res.x);
                        float oy = silu_f((v1 - mean) * rstd * gv[nt].y + bbv[nt].y + res.y);
                        orow16[(c0 + nt * 8) >> 1] = __floats2half2_rn(ox, oy);
                    }
                }
            }
        }
    }
}

// ---------------- node MLP: mma.sync bf16 hi/lo, 512 thr, dual pipelines, prefetch ---
#define W1H_OFF 0
#define W1L_OFF 36864
#define W2H_OFF 73728
#define W2L_OFF 107520
#define AH_OFF  141312
#define AL_OFF  150528
#define TH_OFF  159744
#define TL_OFF  193536
#define RED_OFF 227328
#define MLP2_SMEM 231424
#define NTILE_MLP ((NN + 63) / 64)  // 1563
__global__ __launch_bounds__(512) void mlp_mma_kernel(
    const __half* __restrict__ h16in, const float* __restrict__ W1, const float* __restrict__ b1,
    const float* __restrict__ gg, const float* __restrict__ bn,
    const float* __restrict__ W2, const float* __restrict__ b2, float* __restrict__ hout) {
    extern __shared__ char smem[];
    uint32_t sb = smem_u32(smem);
    float2* sRed = (float2*)(smem + RED_OFF);  // [64 rows][8 warps-in-half]
    int tid = threadIdx.x;
    int w = tid >> 5, lane = tid & 31;
    int halfsel = w >> 3;   // 0: rows 0..31, 1: rows 32..63
    int wl = w & 7;         // warp within half

    // ---- stage weights (threads 0..255 only; once per block)
    if (tid < 256) {
        int n = tid;
        uint32_t dh = sb + W1H_OFF + n * 144;
        uint32_t dl = sb + W1L_OFF + n * 144;
        #pragma unroll
        for (int it = 0; it < 16; it++) {
            int k = it * 4;
            float4 f;
            f.x = __ldg(W1 + (k + 0) * 256 + n);
            f.y = __ldg(W1 + (k + 1) * 256 + n);
            f.z = __ldg(W1 + (k + 2) * 256 + n);
            f.w = __ldg(W1 + (k + 3) * 256 + n);
            uint32_t h01, h23, l01, l23;
            split_pack(f, h01, h23, l01, l23);
            asm volatile("st.shared.v2.u32 [%0], {%1,%2};" :: "r"(dh + k * 2), "r"(h01), "r"(h23));
            asm volatile("st.shared.v2.u32 [%0], {%1,%2};" :: "r"(dl + k * 2), "r"(l01), "r"(l23));
        }
        int n2 = tid & 63, kq = tid >> 6;  // kq 0..3
        uint32_t dh2 = sb + W2H_OFF + n2 * 528 + kq * 128;
        uint32_t dl2 = sb + W2L_OFF + n2 * 528 + kq * 128;
        #pragma unroll
        for (int it = 0; it < 16; it++) {
            int k = kq * 64 + it * 4;
            float4 f;
            f.x = __ldg(W2 + (k + 0) * 64 + n2);
            f.y = __ldg(W2 + (k + 1) * 64 + n2);
            f.z = __ldg(W2 + (k + 2) * 64 + n2);
            f.w = __ldg(W2 + (k + 3) * 64 + n2);
            uint32_t h01, h23, l01, l23;
            split_pack(f, h01, h23, l01, l23);
            asm volatile("st.shared.v2.u32 [%0], {%1,%2};" :: "r"(dh2 + it * 8), "r"(h01), "r"(h23));
            asm volatile("st.shared.v2.u32 [%0], {%1,%2};" :: "r"(dl2 + it * 8), "r"(l01), "r"(l23));
        }
    }

    int c0w = wl * 32 + (lane & 3) * 2;
    float2 b1v[4], gv[4], bnv[4];
    #pragma unroll
    for (int nt = 0; nt < 4; nt++) {
        b1v[nt] = *(const float2*)(b1 + c0w + nt * 8);
        gv[nt] = *(const float2*)(gg + c0w + nt * 8);
        bnv[nt] = *(const float2*)(bn + c0w + nt * 8);
    }
    int rbase = halfsel * 32;  // local row base of this half
    int mblk2 = rbase + (wl & 1) * 16, nblk2 = (wl >> 1) * 16;
    int c02 = nblk2 + (lane & 3) * 2;
    float2 b2v[2];
    b2v[0] = *(const float2*)(b2 + c02);
    b2v[1] = *(const float2*)(b2 + c02 + 8);

    uint32_t aRel = (uint32_t)((rbase + (lane & 15)) * 144 + ((lane >> 4) & 1) * 16);
    uint32_t bRel = (uint32_t)((wl * 32 + ((lane >> 4) & 1) * 8 + (lane & 7)) * 144 +
                               ((lane >> 3) & 1) * 16);
    uint32_t aRel2 = (uint32_t)((mblk2 + (lane & 15)) * 528 + ((lane >> 4) & 1) * 16);
    uint32_t bRel2 = (uint32_t)((nblk2 + ((lane >> 4) & 1) * 8 + (lane & 7)) * 528 +
                                ((lane >> 3) & 1) * 16);
    int srow = tid >> 3, sci = tid & 7;
    uint32_t dA = (uint32_t)(srow * 144 + sci * 16);

    // ---- register prefetch of A rows (16 B per thread)
    uint4 preA;
    {
        int grow = blockIdx.x * 64 + srow;
        preA = make_uint4(0u, 0u, 0u, 0u);
        if (grow < NN)
            preA = *(const uint4*)((const __half2*)(h16in + (long)grow * 64) + sci * 4);
    }

    for (int t = blockIdx.x; t < NTILE_MLP; t += gridDim.x) {
        __syncthreads();
        int base = t * 64;
        // ---- STS from prefetched registers
        {
            __half2 a0 = *(__half2*)&preA.x, a1 = *(__half2*)&preA.y;
            __half2 a2 = *(__half2*)&preA.z, a3 = *(__half2*)&preA.w;
            float2 p0 = __half22float2(a0), p1 = __half22float2(a1);
            float2 p2 = __half22float2(a2), p3 = __half22float2(a3);
            float4 f0 = make_float4(p0.x, p0.y, p1.x, p1.y);
            float4 f1 = make_float4(p2.x, p2.y, p3.x, p3.y);
            uint32_t h01, h23, l01, l23;
            split_pack(f0, h01, h23, l01, l23);
            asm volatile("st.shared.v2.u32 [%0], {%1,%2};" :: "r"(sb + AH_OFF + dA), "r"(h01), "r"(h23));
            asm volatile("st.shared.v2.u32 [%0], {%1,%2};" :: "r"(sb + AL_OFF + dA), "r"(l01), "r"(l23));
            split_pack(f1, h01, h23, l01, l23);
            asm volatile("st.shared.v2.u32 [%0], {%1,%2};" :: "r"(sb + AH_OFF + dA + 8), "r"(h01), "r"(h23));
            asm volatile("st.shared.v2.u32 [%0], {%1,%2};" :: "r"(sb + AL_OFF + dA + 8), "r"(l01), "r"(l23));
        }
        __syncthreads();
        // ---- issue loads for next tile
        int tn = t + gridDim.x;
        if (tn < NTILE_MLP) {
            int grow = tn * 64 + srow;
            preA = make_uint4(0u, 0u, 0u, 0u);
            if (grow < NN)
                preA = *(const uint4*)((const __half2*)(h16in + (long)grow * 64) + sci * 4);
        }

        // ---- G1: this half's 32 rows x 256 cols, warp covers 32r x 32c
        float acc[2][4][4];
        #pragma unroll
        for (int a = 0; a < 2; a++)
            #pragma unroll
            for (int b = 0; b < 4; b++)
                #pragma unroll
                for (int c = 0; c < 4; c++) acc[a][b][c] = 0.f;
        #pragma unroll
        for (int s = 0; s < 4; s++) {
            uint32_t ko = (uint32_t)(s * 32);
            uint32_t ah0[4], ah1[4], al0[4], al1[4];
            ldsm4(ah0, sb + AH_OFF + aRel + ko);
            ldsm4(ah1, sb + AH_OFF + aRel + 2304 + ko);
            ldsm4(al0, sb + AL_OFF + aRel + ko);
            ldsm4(al1, sb + AL_OFF + aRel + 2304 + ko);
            uint32_t bh0[4], bh1[4], bL0[4], bL1[4];
            ldsm4(bh0, sb + W1H_OFF + bRel + ko);
            ldsm4(bh1, sb + W1H_OFF + bRel + 2304 + ko);
            ldsm4(bL0, sb + W1L_OFF + bRel + ko);
            ldsm4(bL1, sb + W1L_OFF + bRel + 2304 + ko);
            #pragma unroll
            for (int nt = 0; nt < 4; nt++) {
                uint32_t bhx0 = (nt < 2) ? bh0[(nt & 1) * 2] : bh1[(nt & 1) * 2];
                uint32_t bhx1 = (nt < 2) ? bh0[(nt & 1) * 2 + 1] : bh1[(nt & 1) * 2 + 1];
                uint32_t blx0 = (nt < 2) ? bL0[(nt & 1) * 2] : bL1[(nt & 1) * 2];
                uint32_t blx1 = (nt < 2) ? bL0[(nt & 1) * 2 + 1] : bL1[(nt & 1) * 2 + 1];
                mma16816(acc[0][nt], ah0, bhx0, bhx1);
                mma16816(acc[0][nt], ah0, blx0, blx1);
                mma16816(acc[0][nt], al0, bhx0, bhx1);
                mma16816(acc[1][nt], ah1, bhx0, bhx1);
                mma16816(acc[1][nt], ah1, blx0, blx1);
                mma16816(acc[1][nt], al1, bhx0, bhx1);
            }
        }
        #pragma unroll
        for (int mt = 0; mt < 2; mt++) {
            #pragma unroll
            for (int nt = 0; nt < 4; nt++) {
                acc[mt][nt][0] = silu_f(acc[mt][nt][0] + b1v[nt].x);
                acc[mt][nt][1] = silu_f(acc[mt][nt][1] + b1v[nt].y);
                acc[mt][nt][2] = silu_f(acc[mt][nt][2] + b1v[nt].x);
                acc[mt][nt][3] = silu_f(acc[mt][nt][3] + b1v[nt].y);
            }
        }
        #pragma unroll
        for (int mt = 0; mt < 2; mt++) {
            #pragma unroll
            for (int h = 0; h < 2; h++) {
                float s = 0.f, q = 0.f;
                #pragma unroll
                for (int nt = 0; nt < 4; nt++) {
                    float v0 = acc[mt][nt][h * 2], v1 = acc[mt][nt][h * 2 + 1];
                    s += v0 + v1;
                    q += v0 * v0 + v1 * v1;
                }
                s += __shfl_xor_sync(0xffffffffu, s, 1);
                q += __shfl_xor_sync(0xffffffffu, q, 1);
                s += __shfl_xor_sync(0xffffffffu, s, 2);
                q += __shfl_xor_sync(0xffffffffu, q, 2);
                if ((lane & 3) == 0) {
                    int r = rbase + mt * 16 + h * 8 + (lane >> 2);
                    sRed[r * 8 + wl] = make_float2(s, q);
                }
            }
        }
        __syncthreads();
        #pragma unroll
        for (int mt = 0; mt < 2; mt++) {
            #pragma unroll
            for (int h = 0; h < 2; h++) {
                int r = rbase + mt * 16 + h * 8 + (lane >> 2);
                float S = 0.f, Q = 0.f;
                #pragma unroll
                for (int ww = 0; ww < 8; ww++) {
                    float2 p = sRed[r * 8 + ww];
                    S += p.x; Q += p.y;
                }
                float mean = S * (1.f / 256.f);
                float var = Q * (1.f / 256.f) - mean * mean;
                float rstd = rsqrtf(var + 1e-5f);
                #pragma unroll
                for (int nt = 0; nt < 4; nt++) {
                    float n0 = (acc[mt][nt][h * 2] - mean) * rstd * gv[nt].x + bnv[nt].x;
                    float n1 = (acc[mt][nt][h * 2 + 1] - mean) * rstd * gv[nt].y + bnv[nt].y;
                    uint32_t h01, l01;
                    split_pack2(n0, n1, h01, l01);
                    uint32_t d = (uint32_t)(r * 528 + (c0w + nt * 8) * 2);
                    asm volatile("st.shared.b32 [%0], %1;" :: "r"(sb + TH_OFF + d), "r"(h01));
                    asm volatile("st.shared.b32 [%0], %1;" :: "r"(sb + TL_OFF + d), "r"(l01));
                }
            }
        }
        __syncthreads();

        // ---- G2: this half's 32 rows x 64 cols, warp covers 16r x 16c
        float acc2[2][4];
        #pragma unroll
        for (int a = 0; a < 2; a++)
            #pragma unroll
            for (int c = 0; c < 4; c++) acc2[a][c] = 0.f;
        #pragma unroll
        for (int s = 0; s < 16; s++) {
            uint32_t ko = (uint32_t)(s * 32);
            uint32_t ah[4], al[4], bh[4], bL[4];
            ldsm4(ah, sb + TH_OFF + aRel2 + ko);
            ldsm4(al, sb + TL_OFF + aRel2 + ko);
            ldsm4(bh, sb + W2H_OFF + bRel2 + ko);
            ldsm4(bL, sb + W2L_OFF + bRel2 + ko);
            #pragma unroll
            for (int nt = 0; nt < 2; nt++) {
                uint32_t bhx0 = bh[nt * 2], bhx1 = bh[nt * 2 + 1];
                uint32_t blx0 = bL[nt * 2], blx1 = bL[nt * 2 + 1];
                mma16816(acc2[nt], ah, bhx0, bhx1);
                mma16816(acc2[nt], ah, blx0, blx1);
                mma16816(acc2[nt], al, bhx0, bhx1);
            }
        }
        #pragma unroll
        for (int nt = 0; nt < 2; nt++) {
            #pragma unroll
            for (int h = 0; h < 2; h++) {
                int r = mblk2 + h * 8 + (lane >> 2);
                int grow = base + r;
                if (grow < NN) {
                    int col = c02 + nt * 8;
                    float2 o;
                    o.x = acc2[nt][h * 2] + b2v[nt].x;
                    o.y = acc2[nt][h * 2 + 1] + b2v[nt].y;
                    *(float2*)(hout + (long)grow * 64 + col) = o;
                }
            }
        }
    }
}

// ---------------- fused pooling + readout: one block per graph ----------------
__global__ __launch_bounds__(256) void pool_readout_kernel(
    const float* __restrict__ h, const float* __restrict__ x, const int* __restrict__ ptr,
    const float* __restrict__ W1, const float* __restrict__ b1,
    const float* __restrict__ gg, const float* __restrict__ bn,
    const float* __restrict__ W2, const float* __restrict__ b2, float* __restrict__ out) {
    int g = blockIdx.x;
    int start = ptr[g], end = ptr[g + 1];
    int tid = threadIdx.x;
    __shared__ float so[196];
    __shared__ float sS[4][64], sM[4][64];
    __shared__ float red[256];
    __shared__ float ws[8][2];
    __shared__ float stats[2];
    {
        int rl = tid >> 6, d = tid & 63;
        float sm = 0.f, mx = -INFINITY;
        for (int r = start + rl; r < end; r += 4) {
            float v = h[(long)r * 64 + d];
            sm += v;
            mx = fmaxf(mx, v);
        }
        sS[rl][d] = sm; sM[rl][d] = mx;
    }
    __syncthreads();
    if (tid < 64) {
        float s = sS[0][tid] + sS[1][tid] + sS[2][tid] + sS[3][tid];
        float m = fmaxf(fmaxf(sM[0][tid], sM[1][tid]), fmaxf(sM[2][tid], sM[3][tid]));
        int cnt = end - start;
        float mean = s / (float)(cnt > 0 ? cnt : 1);
        if (m == -INFINITY) m = 0.f;
        so[tid] = mean;
        so[64 + tid] = m;
        so[128 + tid] = s;
    }
    if (tid < 4) so[192 + tid] = x[(long)start * 4 + tid];
    __syncthreads();
    float acc = __ldg(b1 + tid);
    #pragma unroll 4
    for (int k = 0; k < 196; k++) acc += so[k] * __ldg(W1 + k * 256 + tid);
    float s = silu_f(acc);
    float ls = s, lq = s * s;
    #pragma unroll
    for (int m2 = 1; m2 < 32; m2 <<= 1) {
        ls += __shfl_xor_sync(0xffffffffu, ls, m2);
        lq += __shfl_xor_sync(0xffffffffu, lq, m2);
    }
    int w = tid >> 5;
    if ((tid & 31) == 0) { ws[w][0] = ls; ws[w][1] = lq; }
    __syncthreads();
    if (tid == 0) {
        float S = 0.f, Q = 0.f;
        for (int i = 0; i < 8; i++) { S += ws[i][0]; Q += ws[i][1]; }
        stats[0] = S; stats[1] = Q;
    }
    __syncthreads();
    float mean = stats[0] * (1.f / 256.f);
    float var = stats[1] * (1.f / 256.f) - mean * mean;
    float rstd = rsqrtf(var + 1e-5f);
    float n = (s - mean) * rstd * __ldg(gg + tid) + __ldg(bn + tid);
    float4 w2 = *(const float4*)(W2 + tid * 4);
    float p[4] = {n * w2.x, n * w2.y, n * w2.z, n * w2.w};
    for (int j = 0; j < 4; j++) {
        red[tid] = p[j];
        __syncthreads();
        for (int st = 128; st > 0; st >>= 1) {
            if (tid < st) red[tid] += red[tid + st];
            __syncthreads();
        }
        if (tid == 0) out[g * 4 + j] = red[0] + __ldg(b2 + j);
        __syncthreads();
    }
}

// ---------------- launch ----------------
extern "C" void kernel_launch(void* const* d_in, const int* in_sizes, int n_in,
                              void* d_out, int out_size) {
    const float* x      = (const float*)d_in[0];
    const int*   ei     = (const int*)d_in[1];
    const int*   ptr    = (const int*)d_in[3];
    const float* Wl0    = (const float*)d_in[4];
    const float* bl0    = (const float*)d_in[5];
    const float* Wr0    = (const float*)d_in[6];
    const float* Wl     = (const float*)d_in[7];
    const float* bl     = (const float*)d_in[8];
    const float* Wr     = (const float*)d_in[9];
    const float* Wres   = (const float*)d_in[10];
    const float* bres   = (const float*)d_in[11];
    const float* ln_g   = (const float*)d_in[12];
    const float* ln_b   = (const float*)d_in[13];
    const float* mlp_W1 = (const float*)d_in[14];
    const float* mlp_b1 = (const float*)d_in[15];
    const float* mlp_g  = (const float*)d_in[16];
    const float* mlp_bn = (const float*)d_in[17];
    const float* mlp_W2 = (const float*)d_in[18];
    const float* mlp_b2 = (const float*)d_in[19];
    const float* ro_W1  = (const float*)d_in[20];
    const float* ro_b1  = (const float*)d_in[21];
    const float* ro_g   = (const float*)d_in[22];
    const float* ro_bn  = (const float*)d_in[23];
    const float* ro_W2  = (const float*)d_in[24];
    const float* ro_b2  = (const float*)d_in[25];
    float* out = (float*)d_out;

    void* p;
    cudaGetSymbolAddress(&p, g_deg);    int* deg = (int*)p;
    cudaGetSymbolAddress(&p, g_incl);   int* incl = (int*)p;
    cudaGetSymbolAddress(&p, g_rowptr); int* rowptr = (int*)p;
    cudaGetSymbolAddress(&p, g_cur);    int* cur = (int*)p;
    cudaGetSymbolAddress(&p, g_bsums);  int* bsums = (int*)p;
    cudaGetSymbolAddress(&p, g_csr);    int* csr = (int*)p;
    cudaGetSymbolAddress(&p, g_hA);     float* hA = (float*)p;
    cudaGetSymbolAddress(&p, g_h16A);   __half* h16A = (__half*)p;
    cudaGetSymbolAddress(&p, g_h16B);   __half* h16B = (__half*)p;
    cudaGetSymbolAddress(&p, g_agg16);  __half* agg16 = (__half*)p;

    cudaFuncSetAttribute(sage_mma_kernel, cudaFuncAttributeMaxDynamicSharedMemorySize, MMA_SMEM);
    cudaFuncSetAttribute(mlp_mma_kernel, cudaFuncAttributeMaxDynamicSharedMemorySize, MLP2_SMEM);

    zero_deg_kernel<<<(NN + 255) / 256, 256>>>(deg);
    hist_kernel<<<(NE / 4 + 255) / 256, 256>>>(ei, deg);
    scan1_kernel<<<(NN + 1023) / 1024, 1024>>>(deg, incl, bsums);
    scan3_kernel<<<(NN + 255) / 256, 256>>>(incl, deg, bsums, rowptr, cur);
    scatter_kernel<<<(NE / 4 + 255) / 256, 256>>>(ei, cur, csr);

    layer0_kernel<<<(NN + 3) / 4, 256>>>(x, rowptr, csr, Wl0, bl0, Wr0, Wres, bres,
                                         ln_g, ln_b, h16A);

    const __half* h16in = h16A;
    __half* h16out = h16B;
    for (int i = 0; i < 3; i++) {
        agg_kernel<<<(NN + 7) / 8, 256>>>(h16in, rowptr, csr, agg16);
        sage_mma_kernel<<<296, 256, MMA_SMEM>>>(agg16, h16in, Wl + i * 128 * 64, bl + i * 64,
                                                Wr + i * 64 * 64, ln_g + (i + 1) * 64,
                                                ln_b + (i + 1) * 64, h16out);
        const __half* tmp16 = h16in;
        h16in = h16out;
        h16out = (__half*)tmp16;
    }
    // h16in == final sage output
    mlp_mma_kernel<<<148, 512, MLP2_SMEM>>>(h16in, mlp_W1, mlp_b1, mlp_g, mlp_bn,
                                            mlp_W2, mlp_b2, hA);
    pool_readout_kernel<<<NG, 256>>>(hA, x, ptr, ro_W1, ro_b1, ro_g, ro_bn,
                                     ro_W2, ro_b2, out);
}

// round 17
// speedup vs baseline: 1.6181x; 1.0356x over previous
#include <cuda_runtime.h>
#include <cuda_bf16.h>
#include <cuda_fp16.h>
#include <math.h>
#include <stdint.h>

#define NN 100000
#define NE 1600000
#define NG 200
#define HID 64
#define NB_SCAN 98  // ceil(NN/1024)

// ---------------- scratch (static device globals; no allocation) ----------------
__device__ int   g_deg[NN];
__device__ int   g_incl[NN];
__device__ int   g_rowptr[NN + 1];
__device__ int   g_cur[NN];
__device__ int   g_bsums[256];
__device__ int   g_csr[NE];
__device__ __half g_h16A[NN * HID];
__device__ __half g_h16B[NN * HID];
__device__ __half g_agg16[NN * 128];

__device__ __forceinline__ float silu_f(float z) { return z / (1.f + __expf(-z)); }

__device__ __forceinline__ uint32_t smem_u32(const void* p) {
    uint32_t a;
    asm("{ .reg .u64 t; cvta.to.shared.u64 t, %1; cvt.u32.u64 %0, t; }" : "=r"(a) : "l"(p));
    return a;
}

// hi = truncate-to-bf16 (bit mask), lo = x - hi rounded to bf16. err <= 2^-15 rel.
__device__ __forceinline__ void split_pack(float4 f, uint32_t& h01, uint32_t& h23,
                                           uint32_t& l01, uint32_t& l23) {
    uint32_t x0 = __float_as_uint(f.x), x1 = __float_as_uint(f.y);
    uint32_t x2 = __float_as_uint(f.z), x3 = __float_as_uint(f.w);
    h01 = __byte_perm(x0, x1, 0x7632);
    h23 = __byte_perm(x2, x3, 0x7632);
    float l0 = f.x - __uint_as_float(x0 & 0xFFFF0000u);
    float l1 = f.y - __uint_as_float(x1 & 0xFFFF0000u);
    float l2 = f.z - __uint_as_float(x2 & 0xFFFF0000u);
    float l3 = f.w - __uint_as_float(x3 & 0xFFFF0000u);
    asm("cvt.rn.bf16x2.f32 %0, %1, %2;" : "=r"(l01) : "f"(l1), "f"(l0));
    asm("cvt.rn.bf16x2.f32 %0, %1, %2;" : "=r"(l23) : "f"(l3), "f"(l2));
}

__device__ __forceinline__ void split_pack2(float a, float b, uint32_t& h01, uint32_t& l01) {
    uint32_t x0 = __float_as_uint(a), x1 = __float_as_uint(b);
    h01 = __byte_perm(x0, x1, 0x7632);
    float l0 = a - __uint_as_float(x0 & 0xFFFF0000u);
    float l1 = b - __uint_as_float(x1 & 0xFFFF0000u);
    asm("cvt.rn.bf16x2.f32 %0, %1, %2;" : "=r"(l01) : "f"(l1), "f"(l0));
}

__device__ __forceinline__ void ldsm4(uint32_t* r, uint32_t addr) {
    asm volatile("ldmatrix.sync.aligned.m8n8.x4.shared.b16 {%0,%1,%2,%3}, [%4];"
                 : "=r"(r[0]), "=r"(r[1]), "=r"(r[2]), "=r"(r[3]) : "r"(addr));
}

__device__ __forceinline__ void mma16816(float* c, const uint32_t* a, uint32_t b0, uint32_t b1) {
    asm volatile(
        "mma.sync.aligned.m16n8k16.row.col.f32.bf16.bf16.f32 "
        "{%0,%1,%2,%3}, {%4,%5,%6,%7}, {%8,%9}, {%0,%1,%2,%3};"
        : "+f"(c[0]), "+f"(c[1]), "+f"(c[2]), "+f"(c[3])
        : "r"(a[0]), "r"(a[1]), "r"(a[2]), "r"(a[3]), "r"(b0), "r"(b1));
}

// ---------------- CSR build ----------------
__global__ void zero_deg_kernel(int* deg) {
    int i = blockIdx.x * blockDim.x + threadIdx.x;
    if (i < NN) deg[i] = 0;
}

__global__ void hist_kernel(const int* __restrict__ ei, int* __restrict__ deg) {
    int e = (blockIdx.x * blockDim.x + threadIdx.x) * 4;
    if (e < NE) {  // NE % 4 == 0
        int4 d4 = *(const int4*)(ei + NE + e);
        atomicAdd(&deg[d4.x], 1);
        atomicAdd(&deg[d4.y], 1);
        atomicAdd(&deg[d4.z], 1);
        atomicAdd(&deg[d4.w], 1);
    }
}

// warp-shfl inclusive scan (2 barriers)
__global__ void scan1_kernel(const int* __restrict__ deg, int* __restrict__ incl,
                             int* __restrict__ bsums) {
    __shared__ int sW[32];
    int tid = threadIdx.x;
    int i = blockIdx.x * 1024 + tid;
    int lane = tid & 31, warp = tid >> 5;
    int x = (i < NN) ? deg[i] : 0;
    #pragma unroll
    for (int o = 1; o < 32; o <<= 1) {
        int y = __shfl_up_sync(0xffffffffu, x, o);
        if (lane >= o) x += y;
    }
    if (lane == 31) sW[warp] = x;
    __syncthreads();
    if (warp == 0) {
        int s = sW[lane];
        #pragma unroll
        for (int o = 1; o < 32; o <<= 1) {
            int y = __shfl_up_sync(0xffffffffu, s, o);
            if (lane >= o) s += y;
        }
        sW[lane] = s;
    }
    __syncthreads();
    int inc = x + ((warp > 0) ? sW[warp - 1] : 0);
    if (i < NN) incl[i] = inc;
    if (tid == 1023) bsums[blockIdx.x] = inc;
}

// scan3 with fused block-sum prefix scan (each block redundantly scans the 98 sums)
__global__ void scan3_kernel(const int* __restrict__ incl, const int* __restrict__ deg,
                             const int* __restrict__ bsums, int* __restrict__ rowptr,
                             int* __restrict__ cur) {
    __shared__ int sPre[NB_SCAN];
    int tid = threadIdx.x;
    if (tid < NB_SCAN) sPre[tid] = bsums[tid];
    __syncthreads();
    if (tid == 0) {
        int run = 0;
        #pragma unroll 2
        for (int b = 0; b < NB_SCAN; b++) { int t = sPre[b]; sPre[b] = run; run += t; }
    }
    __syncthreads();
    int i = blockIdx.x * blockDim.x + tid;
    if (i < NN) {
        int val = incl[i] + sPre[i >> 10];
        rowptr[i + 1] = val;
        cur[i] = val - deg[i];
    }
    if (i == 0) rowptr[0] = 0;
}

__global__ void scatter_kernel(const int* __restrict__ ei, int* __restrict__ cur,
                               int* __restrict__ csr) {
    int e = (blockIdx.x * blockDim.x + threadIdx.x) * 4;
    if (e < NE) {
        int4 s4 = *(const int4*)(ei + e);
        int4 d4 = *(const int4*)(ei + NE + e);
        csr[atomicAdd(&cur[d4.x], 1)] = s4.x;
        csr[atomicAdd(&cur[d4.y], 1)] = s4.y;
        csr[atomicAdd(&cur[d4.z], 1)] = s4.z;
        csr[atomicAdd(&cur[d4.w], 1)] = s4.w;
    }
}

// ---------------- layer 0 (IN=4): fully fused sage + LN + x_res + silu ----------------
__global__ __launch_bounds__(256) void layer0_kernel(
    const float* __restrict__ x, const int* __restrict__ rowptr, const int* __restrict__ csr,
    const float* __restrict__ Wl0, const float* __restrict__ bl0, const float* __restrict__ Wr0,
    const float* __restrict__ Wres, const float* __restrict__ bres,
    const float* __restrict__ lng, const float* __restrict__ lnb,
    __half* __restrict__ h16out) {
    int tid = threadIdx.x;
    int grp = tid >> 6;
    int l = tid & 63;
    int v = blockIdx.x * 4 + grp;
    bool valid = (v < NN);
    __shared__ float sMx[4][64], sSm[4][64], sAgg[4][8], sX[4][4], sP[4][2][2];
    int start = 0, end = 0;
    if (valid) { start = rowptr[v]; end = rowptr[v + 1]; }
    if (valid && l < 4) sX[grp][l] = x[v * 4 + l];
    int es = l >> 2, dim = l & 3;
    float mx = -INFINITY, sm = 0.f;
    for (int e = start + es; e < end; e += 16) {
        int s = csr[e];
        float val = x[s * 4 + dim];
        mx = fmaxf(mx, val);
        sm += val;
    }
    sMx[grp][l] = mx; sSm[grp][l] = sm;
    __syncthreads();
    if (l < 8) {
        int dd = l & 3;
        int deg = end - start;
        if (l < 4) {
            float m = -INFINITY;
            #pragma unroll
            for (int j = 0; j < 16; j++) m = fmaxf(m, sMx[grp][j * 4 + dd]);
            sAgg[grp][dd] = (deg > 0) ? m : 0.f;
        } else {
            float s2 = 0.f;
            #pragma unroll
            for (int j = 0; j < 16; j++) s2 += sSm[grp][j * 4 + dd];
            sAgg[grp][4 + dd] = s2 / (float)(deg > 0 ? deg : 1);
        }
    }
    __syncthreads();
    float acc = __ldg(bl0 + l);
    #pragma unroll
    for (int k = 0; k < 8; k++) acc += sAgg[grp][k] * __ldg(Wl0 + k * 64 + l);
    float xres = __ldg(bres + l);
    #pragma unroll
    for (int k = 0; k < 4; k++) {
        float xv = sX[grp][k];
        acc += xv * __ldg(Wr0 + k * 64 + l);
        xres += xv * __ldg(Wres + k * 64 + l);
    }
    float s1 = acc, q1 = acc * acc;
    #pragma unroll
    for (int m2 = 1; m2 < 32; m2 <<= 1) {
        s1 += __shfl_xor_sync(0xffffffffu, s1, m2);
        q1 += __shfl_xor_sync(0xffffffffu, q1, m2);
    }
    int w = (tid >> 5) & 1;
    if ((tid & 31) == 0) { sP[grp][w][0] = s1; sP[grp][w][1] = q1; }
    __syncthreads();
    float S = sP[grp][0][0] + sP[grp][1][0];
    float Q = sP[grp][0][1] + sP[grp][1][1];
    float mean = S * (1.f / 64.f);
    float var = Q * (1.f / 64.f) - mean * mean;
    float rstd = rsqrtf(var + 1e-5f);
    float z = (acc - mean) * rstd * __ldg(lng + l) + __ldg(lnb + l) + xres;
    if (valid) h16out[v * 64 + l] = __float2half(silu_f(z));
}

// ---------------- aggregation: dual-node/warp, uint2 gather (4 dims/lane) ------------
// 16 lanes per node; lane sl owns dims 4sl..4sl+3. Independent scalar index loads,
// 8 independent gathers per node in flight, no shfl in the loop, no final merge.
__global__ __launch_bounds__(256) void agg_kernel(const __half* __restrict__ h16,
                                                  const int* __restrict__ rowptr,
                                                  const int* __restrict__ csr,
                                                  __half* __restrict__ agg16) {
    int tid = threadIdx.x;
    int warp = tid >> 5;
    int lane = tid & 31;
    int h = lane >> 4, sl = lane & 15;
    int v = blockIdx.x * 16 + warp * 2 + h;
    bool valid = (v < NN);
    const uint2* hp2 = (const uint2*)h16;  // node row = 16 uint2 (128 B)
    int start = 0, end = 0;
    if (valid) { start = rowptr[v]; end = rowptr[v + 1]; }
    int deg = end - start;
    float mx0 = -INFINITY, mx1 = -INFINITY, mx2 = -INFINITY, mx3 = -INFINITY;
    float sm0 = 0.f, sm1 = 0.f, sm2 = 0.f, sm3 = 0.f;
    int e = start;
    for (; e + 8 <= end; e += 8) {
        int i0 = csr[e], i1 = csr[e + 1], i2 = csr[e + 2], i3 = csr[e + 3];
        int i4 = csr[e + 4], i5 = csr[e + 5], i6 = csr[e + 6], i7 = csr[e + 7];
        uint2 d0 = hp2[i0 * 16 + sl], d1 = hp2[i1 * 16 + sl];
        uint2 d2 = hp2[i2 * 16 + sl], d3 = hp2[i3 * 16 + sl];
        uint2 d4 = hp2[i4 * 16 + sl], d5 = hp2[i5 * 16 + sl];
        uint2 d6 = hp2[i6 * 16 + sl], d7 = hp2[i7 * 16 + sl];
        #pragma unroll
        for (int j = 0; j < 8; j++) {
            uint2 dd;
            switch (j) {
                case 0: dd = d0; break; case 1: dd = d1; break;
                case 2: dd = d2; break; case 3: dd = d3; break;
                case 4: dd = d4; break; case 5: dd = d5; break;
                case 6: dd = d6; break; default: dd = d7; break;
            }
            float2 f0 = __half22float2(*(__half2*)&dd.x);
            float2 f1 = __half22float2(*(__half2*)&dd.y);
            mx0 = fmaxf(mx0, f0.x); mx1 = fmaxf(mx1, f0.y);
            mx2 = fmaxf(mx2, f1.x); mx3 = fmaxf(mx3, f1.y);
            sm0 += f0.x; sm1 += f0.y; sm2 += f1.x; sm3 += f1.y;
        }
    }
    for (; e < end; e++) {
        int idx = csr[e];
        uint2 dd = hp2[idx * 16 + sl];
        float2 f0 = __half22float2(*(__half2*)&dd.x);
        float2 f1 = __half22float2(*(__half2*)&dd.y);
        mx0 = fmaxf(mx0, f0.x); mx1 = fmaxf(mx1, f0.y);
        mx2 = fmaxf(mx2, f1.x); mx3 = fmaxf(mx3, f1.y);
        sm0 += f0.x; sm1 += f0.y; sm2 += f1.x; sm3 += f1.y;
    }
    if (valid) {
        float inv = 1.f / (float)(deg > 0 ? deg : 1);
        uint2* arow2 = (uint2*)(agg16 + (long)v * 128);  // [mx 0..15 | mean 16..31]
        float a0 = (deg > 0) ? mx0 : 0.f, a1 = (deg > 0) ? mx1 : 0.f;
        float a2 = (deg > 0) ? mx2 : 0.f, a3 = (deg > 0) ? mx3 : 0.f;
        __half2 p0 = __floats2half2_rn(a0, a1), p1 = __floats2half2_rn(a2, a3);
        uint2 om;
        om.x = *(uint32_t*)&p0; om.y = *(uint32_t*)&p1;
        arow2[sl] = om;
        __half2 q0 = __floats2half2_rn(sm0 * inv, sm1 * inv);
        __half2 q1 = __floats2half2_rn(sm2 * inv, sm3 * inv);
        uint2 os;
        os.x = *(uint32_t*)&q0; os.y = *(uint32_t*)&q1;
        arow2[16 + sl] = os;
    }
}

// ---------------- sage hidden layer: mma.sync bf16 hi/lo, M=64, 2/SM, reg-prefetch ---
#define MMA_SMEM 104448
#define NTILE64 ((NN + 63) / 64)
__global__ __launch_bounds__(256) void sage_mma_kernel(
    const __half* __restrict__ agg16, const __half* __restrict__ h16in,
    const float* __restrict__ Wl, const float* __restrict__ bl, const float* __restrict__ Wr,
    const float* __restrict__ lng, const float* __restrict__ lnb,
    __half* __restrict__ h16out) {
    extern __shared__ char smem[];
    uint32_t sbase = smem_u32(smem);
    const uint32_t SAH = sbase, SAL = sbase + 25600;
    const uint32_t SBH = sbase + 51200, SBL = sbase + 76800;
    float2* sRed = (float2*)(smem + 102400);  // [64 rows][4 col-groups]
    int tid = threadIdx.x;

    // ---- stage weights ONCE per block: B[n=64][k=192] hi/lo, row stride 400 B
    {
        int n = tid >> 2, q = tid & 3;
        uint32_t dh = SBH + n * 400 + q * 96;
        uint32_t dl = SBL + n * 400 + q * 96;
        #pragma unroll
        for (int it = 0; it < 12; it++) {
            int k = q * 48 + it * 4;
            float4 f;
            f.x = (k + 0 < 128) ? __ldg(Wl + (k + 0) * 64 + n) : __ldg(Wr + (k - 128) * 64 + n);
            f.y = (k + 1 < 128) ? __ldg(Wl + (k + 1) * 64 + n) : __ldg(Wr + (k - 127) * 64 + n);
            f.z = (k + 2 < 128) ? __ldg(Wl + (k + 2) * 64 + n) : __ldg(Wr + (k - 126) * 64 + n);
            f.w = (k + 3 < 128) ? __ldg(Wl + (k + 3) * 64 + n) : __ldg(Wr + (k - 125) * 64 + n);
            uint32_t h01, h23, l01, l23;
            split_pack(f, h01, h23, l01, l23);
            asm volatile("st.shared.v2.u32 [%0], {%1,%2};" :: "r"(dh + it * 8), "r"(h01), "r"(h23));
            asm volatile("st.shared.v2.u32 [%0], {%1,%2};" :: "r"(dl + it * 8), "r"(l01), "r"(l23));
        }
    }

    int w = tid >> 5, lane = tid & 31;
    int mblk = (w & 1) * 32, nblk = (w >> 1) * 16;
    int wg = w >> 1;  // column group 0..3
    uint32_t aRel = (uint32_t)((mblk + (lane & 15)) * 400 + ((lane >> 4) & 1) * 16);
    uint32_t bRel = (uint32_t)((nblk + ((lane >> 4) & 1) * 8 + (lane & 7)) * 400 +
                               ((lane >> 3) & 1) * 16);
    int c0 = nblk + (lane & 3) * 2;
    float2 blv[2], gv[2], bbv[2];
    #pragma unroll
    for (int nt = 0; nt < 2; nt++) {
        blv[nt] = *(const float2*)(bl + c0 + nt * 8);
        gv[nt] = *(const float2*)(lng + c0 + nt * 8);
        bbv[nt] = *(const float2*)(lnb + c0 + nt * 8);
    }
    int sgrow = tid >> 2, sq = tid & 3;
    uint32_t dhA = SAH + sgrow * 400 + sq * 96;
    uint32_t dlA = SAL + sgrow * 400 + sq * 96;

    // ---- register prefetch of A panel rows (12 x 8B per thread)
    uint2 pre[12];
    {
        int grow = blockIdx.x * 64 + sgrow;
        bool valid = grow < NN;
        const uint2* ar = (const uint2*)(agg16 + (long)grow * 128);
        const uint2* hr = (const uint2*)(h16in + (long)grow * 64);
        #pragma unroll
        for (int it = 0; it < 12; it++) {
            int c = sq * 48 + it * 4;
            uint2 vv = make_uint2(0u, 0u);
            if (valid) vv = (c < 128) ? ar[c >> 2] : hr[(c - 128) >> 2];
            pre[it] = vv;
        }
    }

    for (int t = blockIdx.x; t < NTILE64; t += gridDim.x) {
        __syncthreads();
        int base = t * 64;
        // ---- STS from prefetched registers (convert fp16 -> bf16 hi/lo)
        #pragma unroll
        for (int it = 0; it < 12; it++) {
            __half2 a0 = *(__half2*)&pre[it].x;
            __half2 a1 = *(__half2*)&pre[it].y;
            float2 p0 = __half22float2(a0), p1 = __half22float2(a1);
            float4 f = make_float4(p0.x, p0.y, p1.x, p1.y);
            uint32_t h01, h23, l01, l23;
            split_pack(f, h01, h23, l01, l23);
            asm volatile("st.shared.v2.u32 [%0], {%1,%2};" :: "r"(dhA + it * 8), "r"(h01), "r"(h23));
            asm volatile("st.shared.v2.u32 [%0], {%1,%2};" :: "r"(dlA + it * 8), "r"(l01), "r"(l23));
        }
        __syncthreads();
        // ---- issue loads for next tile (latency hidden under MMA below)
        int tn = t + gridDim.x;
        if (tn < NTILE64) {
            int grow = tn * 64 + sgrow;
            bool valid = grow < NN;
            const uint2* ar = (const uint2*)(agg16 + (long)grow * 128);
            const uint2* hr = (const uint2*)(h16in + (long)grow * 64);
            #pragma unroll
            for (int it = 0; it < 12; it++) {
                int c = sq * 48 + it * 4;
                uint2 vv = make_uint2(0u, 0u);
                if (valid) vv = (c < 128) ? ar[c >> 2] : hr[(c - 128) >> 2];
                pre[it] = vv;
            }
        }

        float acc[2][2][4];
        #pragma unroll
        for (int a = 0; a < 2; a++)
            #pragma unroll
            for (int b = 0; b < 2; b++)
                #pragma unroll
                for (int c = 0; c < 4; c++) acc[a][b][c] = 0.f;

        #pragma unroll
        for (int s = 0; s < 12; s++) {
            uint32_t ko = (uint32_t)(s * 32);
            uint32_t ah0[4], ah1[4], al0[4], al1[4];
            ldsm4(ah0, SAH + aRel + ko);
            ldsm4(ah1, SAH + aRel + 6400 + ko);
            ldsm4(al0, SAL + aRel + ko);
            ldsm4(al1, SAL + aRel + 6400 + ko);
            uint32_t bh[4], bL[4];
            ldsm4(bh, SBH + bRel + ko);
            ldsm4(bL, SBL + bRel + ko);
            #pragma unroll
            for (int nt = 0; nt < 2; nt++) {
                uint32_t bhx0 = bh[nt * 2], bhx1 = bh[nt * 2 + 1];
                uint32_t blx0 = bL[nt * 2], blx1 = bL[nt * 2 + 1];
                mma16816(acc[0][nt], ah0, bhx0, bhx1);
                mma16816(acc[0][nt], ah0, blx0, blx1);
                mma16816(acc[0][nt], al0, bhx0, bhx1);
                mma16816(acc[1][nt], ah1, bhx0, bhx1);
                mma16816(acc[1][nt], ah1, blx0, blx1);
                mma16816(acc[1][nt], al1, bhx0, bhx1);
            }
        }

        #pragma unroll
        for (int mt = 0; mt < 2; mt++)
            #pragma unroll
            for (int nt = 0; nt < 2; nt++) {
                acc[mt][nt][0] += blv[nt].x; acc[mt][nt][1] += blv[nt].y;
                acc[mt][nt][2] += blv[nt].x; acc[mt][nt][3] += blv[nt].y;
            }
        #pragma unroll
        for (int mt = 0; mt < 2; mt++) {
            #pragma unroll
            for (int h = 0; h < 2; h++) {
                float s = 0.f, q = 0.f;
                #pragma unroll
                for (int nt = 0; nt < 2; nt++) {
                    float v0 = acc[mt][nt][h * 2], v1 = acc[mt][nt][h * 2 + 1];
                    s += v0 + v1;
                    q += v0 * v0 + v1 * v1;
                }
                s += __shfl_xor_sync(0xffffffffu, s, 1);
                q += __shfl_xor_sync(0xffffffffu, q, 1);
                s += __shfl_xor_sync(0xffffffffu, s, 2);
                q += __shfl_xor_sync(0xffffffffu, q, 2);
                if ((lane & 3) == 0) {
                    int r = mblk + mt * 16 + h * 8 + (lane >> 2);
                    sRed[r * 4 + wg] = make_float2(s, q);
                }
            }
        }
        __syncthreads();
        #pragma unroll
        for (int mt = 0; mt < 2; mt++) {
            #pragma unroll
            for (int h = 0; h < 2; h++) {
                int r = mblk + mt * 16 + h * 8 + (lane >> 2);
                float2 p0 = sRed[r * 4 + 0], p1 = sRed[r * 4 + 1];
                float2 p2 = sRed[r * 4 + 2], p3 = sRed[r * 4 + 3];
                float S = (p0.x + p1.x) + (p2.x + p3.x);
                float Q = (p0.y + p1.y) + (p2.y + p3.y);
                float mean = S * (1.f / 64.f);
                float var = Q * (1.f / 64.f) - mean * mean;
                float rstd = rsqrtf(var + 1e-5f);
                int grow = base + r;
                if (grow < NN) {
                    __half2* orow16 = (__half2*)(h16out + (long)grow * 64);
                    const __half2* rrow = (const __half2*)(h16in + (long)grow * 64);
                    #pragma unroll
                    for (int nt = 0; nt < 2; nt++) {
                        float2 res = __half22float2(rrow[(c0 + nt * 8) >> 1]);
                        float v0 = acc[mt][nt][h * 2], v1 = acc[mt][nt][h * 2 + 1];
                        float ox = silu_f((v0 - mean) * rstd * gv[nt].x + bbv[nt].x + res.x);
                        float oy = silu_f((v1 - mean) * rstd * gv[nt].y + bbv[nt].y + res.y);
                        orow16[(c0 + nt * 8) >> 1] = __floats2half2_rn(ox, oy);
                    }
                }
            }
        }
    }
}

// ---------------- node MLP: mma.sync bf16 hi/lo, 512 thr, dual pipelines, prefetch ---
#define W1H_OFF 0
#define W1L_OFF 36864
#define W2H_OFF 73728
#define W2L_OFF 107520
#define AH_OFF  141312
#define AL_OFF  150528
#define TH_OFF  159744
#define TL_OFF  193536
#define RED_OFF 227328
#define MLP2_SMEM 231424
#define NTILE_MLP ((NN + 63) / 64)  // 1563
__global__ __launch_bounds__(512) void mlp_mma_kernel(
    const __half* __restrict__ h16in, const float* __restrict__ W1, const float* __restrict__ b1,
    const float* __restrict__ gg, const float* __restrict__ bn,
    const float* __restrict__ W2, const float* __restrict__ b2, __half* __restrict__ hout) {
    extern __shared__ char smem[];
    uint32_t sb = smem_u32(smem);
    float2* sRed = (float2*)(smem + RED_OFF);  // [64 rows][8 warps-in-half]
    int tid = threadIdx.x;
    int w = tid >> 5, lane = tid & 31;
    int halfsel = w >> 3;   // 0: rows 0..31, 1: rows 32..63
    int wl = w & 7;         // warp within half

    // ---- stage weights (threads 0..255 only; once per block)
    if (tid < 256) {
        int n = tid;
        uint32_t dh = sb + W1H_OFF + n * 144;
        uint32_t dl = sb + W1L_OFF + n * 144;
        #pragma unroll
        for (int it = 0; it < 16; it++) {
            int k = it * 4;
            float4 f;
            f.x = __ldg(W1 + (k + 0) * 256 + n);
            f.y = __ldg(W1 + (k + 1) * 256 + n);
            f.z = __ldg(W1 + (k + 2) * 256 + n);
            f.w = __ldg(W1 + (k + 3) * 256 + n);
            uint32_t h01, h23, l01, l23;
            split_pack(f, h01, h23, l01, l23);
            asm volatile("st.shared.v2.u32 [%0], {%1,%2};" :: "r"(dh + k * 2), "r"(h01), "r"(h23));
            asm volatile("st.shared.v2.u32 [%0], {%1,%2};" :: "r"(dl + k * 2), "r"(l01), "r"(l23));
        }
        int n2 = tid & 63, kq = tid >> 6;  // kq 0..3
        uint32_t dh2 = sb + W2H_OFF + n2 * 528 + kq * 128;
        uint32_t dl2 = sb + W2L_OFF + n2 * 528 + kq * 128;
        #pragma unroll
        for (int it = 0; it < 16; it++) {
            int k = kq * 64 + it * 4;
            float4 f;
            f.x = __ldg(W2 + (k + 0) * 64 + n2);
            f.y = __ldg(W2 + (k + 1) * 64 + n2);
            f.z = __ldg(W2 + (k + 2) * 64 + n2);
            f.w = __ldg(W2 + (k + 3) * 64 + n2);
            uint32_t h01, h23, l01, l23;
            split_pack(f, h01, h23, l01, l23);
            asm volatile("st.shared.v2.u32 [%0], {%1,%2};" :: "r"(dh2 + it * 8), "r"(h01), "r"(h23));
            asm volatile("st.shared.v2.u32 [%0], {%1,%2};" :: "r"(dl2 + it * 8), "r"(l01), "r"(l23));
        }
    }

    int c0w = wl * 32 + (lane & 3) * 2;
    float2 b1v[4], gv[4], bnv[4];
    #pragma unroll
    for (int nt = 0; nt < 4; nt++) {
        b1v[nt] = *(const float2*)(b1 + c0w + nt * 8);
        gv[nt] = *(const float2*)(gg + c0w + nt * 8);
        bnv[nt] = *(const float2*)(bn + c0w + nt * 8);
    }
    int rbase = halfsel * 32;  // local row base of this half
    int mblk2 = rbase + (wl & 1) * 16, nblk2 = (wl >> 1) * 16;
    int c02 = nblk2 + (lane & 3) * 2;
    float2 b2v[2];
    b2v[0] = *(const float2*)(b2 + c02);
    b2v[1] = *(const float2*)(b2 + c02 + 8);

    uint32_t aRel = (uint32_t)((rbase + (lane & 15)) * 144 + ((lane >> 4) & 1) * 16);
    uint32_t bRel = (uint32_t)((wl * 32 + ((lane >> 4) & 1) * 8 + (lane & 7)) * 144 +
                               ((lane >> 3) & 1) * 16);
    uint32_t aRel2 = (uint32_t)((mblk2 + (lane & 15)) * 528 + ((lane >> 4) & 1) * 16);
    uint32_t bRel2 = (uint32_t)((nblk2 + ((lane >> 4) & 1) * 8 + (lane & 7)) * 528 +
                                ((lane >> 3) & 1) * 16);
    int srow = tid >> 3, sci = tid & 7;
    uint32_t dA = (uint32_t)(srow * 144 + sci * 16);

    // ---- register prefetch of A rows (16 B per thread)
    uint4 preA;
    {
        int grow = blockIdx.x * 64 + srow;
        preA = make_uint4(0u, 0u, 0u, 0u);
        if (grow < NN)
            preA = *(const uint4*)((const __half2*)(h16in + (long)grow * 64) + sci * 4);
    }

    for (int t = blockIdx.x; t < NTILE_MLP; t += gridDim.x) {
        __syncthreads();
        int base = t * 64;
        // ---- STS from prefetched registers
        {
            __half2 a0 = *(__half2*)&preA.x, a1 = *(__half2*)&preA.y;
            __half2 a2 = *(__half2*)&preA.z, a3 = *(__half2*)&preA.w;
            float2 p0 = __half22float2(a0), p1 = __half22float2(a1);
            float2 p2 = __half22float2(a2), p3 = __half22float2(a3);
            float4 f0 = make_float4(p0.x, p0.y, p1.x, p1.y);
            float4 f1 = make_float4(p2.x, p2.y, p3.x, p3.y);
            uint32_t h01, h23, l01, l23;
            split_pack(f0, h01, h23, l01, l23);
            asm volatile("st.shared.v2.u32 [%0], {%1,%2};" :: "r"(sb + AH_OFF + dA), "r"(h01), "r"(h23));
            asm volatile("st.shared.v2.u32 [%0], {%1,%2};" :: "r"(sb + AL_OFF + dA), "r"(l01), "r"(l23));
            split_pack(f1, h01, h23, l01, l23);
            asm volatile("st.shared.v2.u32 [%0], {%1,%2};" :: "r"(sb + AH_OFF + dA + 8), "r"(h01), "r"(h23));
            asm volatile("st.shared.v2.u32 [%0], {%1,%2};" :: "r"(sb + AL_OFF + dA + 8), "r"(l01), "r"(l23));
        }
        __syncthreads();
        // ---- issue loads for next tile
        int tn = t + gridDim.x;
        if (tn < NTILE_MLP) {
            int grow = tn * 64 + srow;
            preA = make_uint4(0u, 0u, 0u, 0u);
            if (grow < NN)
                preA = *(const uint4*)((const __half2*)(h16in + (long)grow * 64) + sci * 4);
        }

        // ---- G1: this half's 32 rows x 256 cols, warp covers 32r x 32c
        float acc[2][4][4];
        #pragma unroll
        for (int a = 0; a < 2; a++)
            #pragma unroll
            for (int b = 0; b < 4; b++)
                #pragma unroll
                for (int c = 0; c < 4; c++) acc[a][b][c] = 0.f;
        #pragma unroll
        for (int s = 0; s < 4; s++) {
            uint32_t ko = (uint32_t)(s * 32);
            uint32_t ah0[4], ah1[4], al0[4], al1[4];
            ldsm4(ah0, sb + AH_OFF + aRel + ko);
            ldsm4(ah1, sb + AH_OFF + aRel + 2304 + ko);
            ldsm4(al0, sb + AL_OFF + aRel + ko);
            ldsm4(al1, sb + AL_OFF + aRel + 2304 + ko);
            uint32_t bh0[4], bh1[4], bL0[4], bL1[4];
            ldsm4(bh0, sb + W1H_OFF + bRel + ko);
            ldsm4(bh1, sb + W1H_OFF + bRel + 2304 + ko);
            ldsm4(bL0, sb + W1L_OFF + bRel + ko);
            ldsm4(bL1, sb + W1L_OFF + bRel + 2304 + ko);
            #pragma unroll
            for (int nt = 0; nt < 4; nt++) {
                uint32_t bhx0 = (nt < 2) ? bh0[(nt & 1) * 2] : bh1[(nt & 1) * 2];
                uint32_t bhx1 = (nt < 2) ? bh0[(nt & 1) * 2 + 1] : bh1[(nt & 1) * 2 + 1];
                uint32_t blx0 = (nt < 2) ? bL0[(nt & 1) * 2] : bL1[(nt & 1) * 2];
                uint32_t blx1 = (nt < 2) ? bL0[(nt & 1) * 2 + 1] : bL1[(nt & 1) * 2 + 1];
                mma16816(acc[0][nt], ah0, bhx0, bhx1);
                mma16816(acc[0][nt], ah0, blx0, blx1);
                mma16816(acc[0][nt], al0, bhx0, bhx1);
                mma16816(acc[1][nt], ah1, bhx0, bhx1);
                mma16816(acc[1][nt], ah1, blx0, blx1);
                mma16816(acc[1][nt], al1, bhx0, bhx1);
            }
        }
        #pragma unroll
        for (int mt = 0; mt < 2; mt++) {
            #pragma unroll
            for (int nt = 0; nt < 4; nt++) {
                acc[mt][nt][0] = silu_f(acc[mt][nt][0] + b1v[nt].x);
                acc[mt][nt][1] = silu_f(acc[mt][nt][1] + b1v[nt].y);
                acc[mt][nt][2] = silu_f(acc[mt][nt][2] + b1v[nt].x);
                acc[mt][nt][3] = silu_f(acc[mt][nt][3] + b1v[nt].y);
            }
        }
        #pragma unroll
        for (int mt = 0; mt < 2; mt++) {
            #pragma unroll
            for (int h = 0; h < 2; h++) {
                float s = 0.f, q = 0.f;
                #pragma unroll
                for (int nt = 0; nt < 4; nt++) {
                    float v0 = acc[mt][nt][h * 2], v1 = acc[mt][nt][h * 2 + 1];
                    s += v0 + v1;
                    q += v0 * v0 + v1 * v1;
                }
                s += __shfl_xor_sync(0xffffffffu, s, 1);
                q += __shfl_xor_sync(0xffffffffu, q, 1);
                s += __shfl_xor_sync(0xffffffffu, s, 2);
                q += __shfl_xor_sync(0xffffffffu, q, 2);
                if ((lane & 3) == 0) {
                    int r = rbase + mt * 16 + h * 8 + (lane >> 2);
                    sRed[r * 8 + wl] = make_float2(s, q);
                }
            }
        }
        __syncthreads();
        #pragma unroll
        for (int mt = 0; mt < 2; mt++) {
            #pragma unroll
            for (int h = 0; h < 2; h++) {
                int r = rbase + mt * 16 + h * 8 + (lane >> 2);
                float S = 0.f, Q = 0.f;
                #pragma unroll
                for (int ww = 0; ww < 8; ww++) {
                    float2 p = sRed[r * 8 + ww];
                    S += p.x; Q += p.y;
                }
                float mean = S * (1.f / 256.f);
                float var = Q * (1.f / 256.f) - mean * mean;
                float rstd = rsqrtf(var + 1e-5f);
                #pragma unroll
                for (int nt = 0; nt < 4; nt++) {
                    float n0 = (acc[mt][nt][h * 2] - mean) * rstd * gv[nt].x + bnv[nt].x;
                    float n1 = (acc[mt][nt][h * 2 + 1] - mean) * rstd * gv[nt].y + bnv[nt].y;
                    uint32_t h01, l01;
                    split_pack2(n0, n1, h01, l01);
                    uint32_t d = (uint32_t)(r * 528 + (c0w + nt * 8) * 2);
                    asm volatile("st.shared.b32 [%0], %1;" :: "r"(sb + TH_OFF + d), "r"(h01));
                    asm volatile("st.shared.b32 [%0], %1;" :: "r"(sb + TL_OFF + d), "r"(l01));
                }
            }
        }
        __syncthreads();

        // ---- G2: this half's 32 rows x 64 cols, warp covers 16r x 16c
        float acc2[2][4];
        #pragma unroll
        for (int a = 0; a < 2; a++)
            #pragma unroll
            for (int c = 0; c < 4; c++) acc2[a][c] = 0.f;
        #pragma unroll
        for (int s = 0; s < 16; s++) {
            uint32_t ko = (uint32_t)(s * 32);
            uint32_t ah[4], al[4], bh[4], bL[4];
            ldsm4(ah, sb + TH_OFF + aRel2 + ko);
            ldsm4(al, sb + TL_OFF + aRel2 + ko);
            ldsm4(bh, sb + W2H_OFF + bRel2 + ko);
            ldsm4(bL, sb + W2L_OFF + bRel2 + ko);
            #pragma unroll
            for (int nt = 0; nt < 2; nt++) {
                uint32_t bhx0 = bh[nt * 2], bhx1 = bh[nt * 2 + 1];
                uint32_t blx0 = bL[nt * 2], blx1 = bL[nt * 2 + 1];
                mma16816(acc2[nt], ah, bhx0, bhx1);
                mma16816(acc2[nt], ah, blx0, blx1);
                mma16816(acc2[nt], al, bhx0, bhx1);
            }
        }
        #pragma unroll
        for (int nt = 0; nt < 2; nt++) {
            #pragma unroll
            for (int h = 0; h < 2; h++) {
                int r = mblk2 + h * 8 + (lane >> 2);
                int grow = base + r;
                if (grow < NN) {
                    int col = c02 + nt * 8;
                    float ox = acc2[nt][h * 2] + b2v[nt].x;
                    float oy = acc2[nt][h * 2 + 1] + b2v[nt].y;
                    ((__half2*)(hout + (long)grow * 64))[col >> 1] = __floats2half2_rn(ox, oy);
                }
            }
        }
    }
}

// ---------------- fused pooling + readout: one block per graph (fp16 h) --------------
__global__ __launch_bounds__(256) void pool_readout_kernel(
    const __half* __restrict__ h, const float* __restrict__ x, const int* __restrict__ ptr,
    const float* __restrict__ W1, const float* __restrict__ b1,
    const float* __restrict__ gg, const float* __restrict__ bn,
    const float* __restrict__ W2, const float* __restrict__ b2, float* __restrict__ out) {
    int g = blockIdx.x;
    int start = ptr[g], end = ptr[g + 1];
    int tid = threadIdx.x;
    __shared__ float so[196];
    __shared__ float sS[4][64], sM[4][64];
    __shared__ float red[256];
    __shared__ float ws[8][2];
    __shared__ float stats[2];
    {
        int rl = tid >> 6, d = tid & 63;
        float sm = 0.f, mx = -INFINITY;
        for (int r = start + rl; r < end; r += 4) {
            float v = __half2float(h[(long)r * 64 + d]);
            sm += v;
            mx = fmaxf(mx, v);
        }
        sS[rl][d] = sm; sM[rl][d] = mx;
    }
    __syncthreads();
    if (tid < 64) {
        float s = sS[0][tid] + sS[1][tid] + sS[2][tid] + sS[3][tid];
        float m = fmaxf(fmaxf(sM[0][tid], sM[1][tid]), fmaxf(sM[2][tid], sM[3][tid]));
        int cnt = end - start;
        float mean = s / (float)(cnt > 0 ? cnt : 1);
        if (m == -INFINITY) m = 0.f;
        so[tid] = mean;
        so[64 + tid] = m;
        so[128 + tid] = s;
    }
    if (tid < 4) so[192 + tid] = x[(long)start * 4 + tid];
    __syncthreads();
    float acc = __ldg(b1 + tid);
    #pragma unroll 4
    for (int k = 0; k < 196; k++) acc += so[k] * __ldg(W1 + k * 256 + tid);
    float s = silu_f(acc);
    float ls = s, lq = s * s;
    #pragma unroll
    for (int m2 = 1; m2 < 32; m2 <<= 1) {
        ls += __shfl_xor_sync(0xffffffffu, ls, m2);
        lq += __shfl_xor_sync(0xffffffffu, lq, m2);
    }
    int w = tid >> 5;
    if ((tid & 31) == 0) { ws[w][0] = ls; ws[w][1] = lq; }
    __syncthreads();
    if (tid == 0) {
        float S = 0.f, Q = 0.f;
        for (int i = 0; i < 8; i++) { S += ws[i][0]; Q += ws[i][1]; }
        stats[0] = S; stats[1] = Q;
    }
    __syncthreads();
    float mean = stats[0] * (1.f / 256.f);
    float var = stats[1] * (1.f / 256.f) - mean * mean;
    float rstd = rsqrtf(var + 1e-5f);
    float n = (s - mean) * rstd * __ldg(gg + tid) + __ldg(bn + tid);
    float4 w2 = *(const float4*)(W2 + tid * 4);
    float p[4] = {n * w2.x, n * w2.y, n * w2.z, n * w2.w};
    for (int j = 0; j < 4; j++) {
        red[tid] = p[j];
        __syncthreads();
        for (int st = 128; st > 0; st >>= 1) {
            if (tid < st) red[tid] += red[tid + st];
            __syncthreads();
        }
        if (tid == 0) out[g * 4 + j] = red[0] + __ldg(b2 + j);
        __syncthreads();
    }
}

// ---------------- launch ----------------
extern "C" void kernel_launch(void* const* d_in, const int* in_sizes, int n_in,
                              void* d_out, int out_size) {
    const float* x      = (const float*)d_in[0];
    const int*   ei     = (const int*)d_in[1];
    const int*   ptr    = (const int*)d_in[3];
    const float* Wl0    = (const float*)d_in[4];
    const float* bl0    = (const float*)d_in[5];
    const float* Wr0    = (const float*)d_in[6];
    const float* Wl     = (const float*)d_in[7];
    const float* bl     = (const float*)d_in[8];
    const float* Wr     = (const float*)d_in[9];
    const float* Wres   = (const float*)d_in[10];
    const float* bres   = (const float*)d_in[11];
    const float* ln_g   = (const float*)d_in[12];
    const float* ln_b   = (const float*)d_in[13];
    const float* mlp_W1 = (const float*)d_in[14];
    const float* mlp_b1 = (const float*)d_in[15];
    const float* mlp_g  = (const float*)d_in[16];
    const float* mlp_bn = (const float*)d_in[17];
    const float* mlp_W2 = (const float*)d_in[18];
    const float* mlp_b2 = (const float*)d_in[19];
    const float* ro_W1  = (const float*)d_in[20];
    const float* ro_b1  = (const float*)d_in[21];
    const float* ro_g   = (const float*)d_in[22];
    const float* ro_bn  = (const float*)d_in[23];
    const float* ro_W2  = (const float*)d_in[24];
    const float* ro_b2  = (const float*)d_in[25];
    float* out = (float*)d_out;

    void* p;
    cudaGetSymbolAddress(&p, g_deg);    int* deg = (int*)p;
    cudaGetSymbolAddress(&p, g_incl);   int* incl = (int*)p;
    cudaGetSymbolAddress(&p, g_rowptr); int* rowptr = (int*)p;
    cudaGetSymbolAddress(&p, g_cur);    int* cur = (int*)p;
    cudaGetSymbolAddress(&p, g_bsums);  int* bsums = (int*)p;
    cudaGetSymbolAddress(&p, g_csr);    int* csr = (int*)p;
    cudaGetSymbolAddress(&p, g_h16A);   __half* h16A = (__half*)p;
    cudaGetSymbolAddress(&p, g_h16B);   __half* h16B = (__half*)p;
    cudaGetSymbolAddress(&p, g_agg16);  __half* agg16 = (__half*)p;

    cudaFuncSetAttribute(sage_mma_kernel, cudaFuncAttributeMaxDynamicSharedMemorySize, MMA_SMEM);
    cudaFuncSetAttribute(mlp_mma_kernel, cudaFuncAttributeMaxDynamicSharedMemorySize, MLP2_SMEM);

    zero_deg_kernel<<<(NN + 255) / 256, 256>>>(deg);
    hist_kernel<<<(NE / 4 + 255) / 256, 256>>>(ei, deg);
    scan1_kernel<<<(NN + 1023) / 1024, 1024>>>(deg, incl, bsums);
    scan3_kernel<<<(NN + 255) / 256, 256>>>(incl, deg, bsums, rowptr, cur);
    scatter_kernel<<<(NE / 4 + 255) / 256, 256>>>(ei, cur, csr);

    layer0_kernel<<<(NN + 3) / 4, 256>>>(x, rowptr, csr, Wl0, bl0, Wr0, Wres, bres,
                                         ln_g, ln_b, h16A);

    const __half* h16in = h16A;
    __half* h16out = h16B;
    for (int i = 0; i < 3; i++) {
        agg_kernel<<<(NN + 15) / 16, 256>>>(h16in, rowptr, csr, agg16);
        sage_mma_kernel<<<296, 256, MMA_SMEM>>>(agg16, h16in, Wl + i * 128 * 64, bl + i * 64,
                                                Wr + i * 64 * 64, ln_g + (i + 1) * 64,
                                                ln_b + (i + 1) * 64, h16out);
        const __half* tmp16 = h16in;
        h16in = h16out;
        h16out = (__half*)tmp16;
    }
    // h16in == final sage output (h16B); h16out (h16A) is free -> mlp fp16 output
    mlp_mma_kernel<<<148, 512, MLP2_SMEM>>>(h16in, mlp_W1, mlp_b1, mlp_g, mlp_bn,
                                            mlp_W2, mlp_b2, h16out);
    pool_readout_kernel<<<NG, 256>>>(h16out, x, ptr, ro_W1, ro_b1, ro_g, ro_bn,
                                     ro_W2, ro_b2, out);
}